// round 12
// baseline (speedup 1.0000x reference)
#include <cuda_runtime.h>
#include <math.h>

#define NTOK 16384
#define DDIM 256
#define KCB  512
#define LLV  8
#define BATCH 16

// ---------------- device scratch (static, no allocations) ----------------
__device__ float g_S[NTOK * KCB];      // raw dot[n,k] for current level (32 MB)
__device__ float g_g[DDIM];            // global_sum, fp32, reference-exact chain
__device__ float g_rss[NTOK];          // ||fl(z-g)||^2 per token (current level)
__device__ float g_wss[LLV * KCB];     // ||W_k||^2
__device__ float g_normW[LLV * KCB];   // ||W_k||
__device__ float g_kl[NTOK];           // kl accumulator
__device__ int   g_idx[NTOK * LLV];    // picks (strided by level)
__device__ int   g_pidx[NTOK];         // packed picks for current level
__device__ float g_ltok[NTOK];         // per-token loss

typedef unsigned long long ull;
struct __align__(16) u64x2 { ull a, b; };

__device__ __forceinline__ ull pk2(float lo, float hi) {
    ull r;
    asm("mov.b64 %0, {%1, %2};" : "=l"(r) : "f"(lo), "f"(hi));
    return r;
}
__device__ __forceinline__ void upk2(ull v, float& lo, float& hi) {
    asm("mov.b64 {%0, %1}, %2;" : "=f"(lo), "=f"(hi) : "l"(v));
}
__device__ __forceinline__ ull ffma2(ull a, ull b, ull c) {
    ull d;
    asm("fma.rn.f32x2 %0, %1, %2, %3;" : "=l"(d) : "l"(a), "l"(b), "l"(c));
    return d;
}

// ---------------- init: wss, norms, zero g ----------------
__global__ void k_init(const float* __restrict__ W) {
    int gid = blockIdx.x * blockDim.x + threadIdx.x;   // 16*256 = 4096
    if (gid < LLV * KCB) {
        const float4* row = (const float4*)(W + (size_t)gid * DDIM);
        float acc = 0.f;
        #pragma unroll 8
        for (int j = 0; j < DDIM / 4; j++) {
            float4 w4 = row[j];
            acc = __fadd_rn(acc, __fmul_rn(w4.x, w4.x));
            acc = __fadd_rn(acc, __fmul_rn(w4.y, w4.y));
            acc = __fadd_rn(acc, __fmul_rn(w4.z, w4.z));
            acc = __fadd_rn(acc, __fmul_rn(w4.w, w4.w));
        }
        g_wss[gid]   = acc;
        g_normW[gid] = sqrtf(acc);
    }
    if (gid < DDIM) g_g[gid] = 0.f;
}

// ---------------- GEMM (bit-frozen, round-10 verbatim): 128x128 tile, BK=16 -------
__global__ __launch_bounds__(256, 2) void k_gemm(const float* __restrict__ Z,
                                                 const float* __restrict__ W) {
    __shared__ __align__(16) float As[2][16][132];
    __shared__ __align__(16) float Bs[2][16][132];
    __shared__ float sg[DDIM];
    int tid = threadIdx.x;
    int bx = blockIdx.x, by = blockIdx.y;   // bx 0..3, by 0..127
    int tx = tid & 15, ty = tid >> 4;
    int ty4 = ty * 4, tx4 = tx * 4;
    int lrow = tid >> 2;                    // 0..63
    int lc4  = (tid & 3) * 4;               // 0,4,8,12
    const int RO = 64 * DDIM;               // +64 rows
    const float* Ap = Z + (size_t)(by * 128 + lrow) * DDIM + lc4;
    const float* Bp = W + (size_t)(bx * 128 + lrow) * DDIM + lc4;

    sg[tid] = g_g[tid];

    ull acc2[4][8];   // row-pairs x 8 cols
    #pragma unroll
    for (int p = 0; p < 4; p++)
        #pragma unroll
        for (int j = 0; j < 8; j++) acc2[p][j] = 0ull;

    float4 a0 = *(const float4*)Ap;
    float4 a1 = *(const float4*)(Ap + RO);
    float4 b0 = *(const float4*)Bp;
    float4 b1 = *(const float4*)(Bp + RO);
    __syncthreads();                          // sg visible

    {
        As[0][lc4 + 0][lrow] = __fsub_rn(a0.x, sg[lc4 + 0]);
        As[0][lc4 + 1][lrow] = __fsub_rn(a0.y, sg[lc4 + 1]);
        As[0][lc4 + 2][lrow] = __fsub_rn(a0.z, sg[lc4 + 2]);
        As[0][lc4 + 3][lrow] = __fsub_rn(a0.w, sg[lc4 + 3]);
        As[0][lc4 + 0][64 + lrow] = __fsub_rn(a1.x, sg[lc4 + 0]);
        As[0][lc4 + 1][64 + lrow] = __fsub_rn(a1.y, sg[lc4 + 1]);
        As[0][lc4 + 2][64 + lrow] = __fsub_rn(a1.z, sg[lc4 + 2]);
        As[0][lc4 + 3][64 + lrow] = __fsub_rn(a1.w, sg[lc4 + 3]);
        Bs[0][lc4 + 0][lrow] = b0.x; Bs[0][lc4 + 1][lrow] = b0.y;
        Bs[0][lc4 + 2][lrow] = b0.z; Bs[0][lc4 + 3][lrow] = b0.w;
        Bs[0][lc4 + 0][64 + lrow] = b1.x; Bs[0][lc4 + 1][64 + lrow] = b1.y;
        Bs[0][lc4 + 2][64 + lrow] = b1.z; Bs[0][lc4 + 3][64 + lrow] = b1.w;
    }
    a0 = *(const float4*)(Ap + 16);          // prefetch tile 1
    a1 = *(const float4*)(Ap + 16 + RO);
    b0 = *(const float4*)(Bp + 16);
    b1 = *(const float4*)(Bp + 16 + RO);
    __syncthreads();

    for (int t = 0; t < 16; t++) {
        int buf = t & 1;
        if (t + 1 < 16) {
            int nb = (t + 1) & 1;
            int k1 = (t + 1) * 16;
            As[nb][lc4 + 0][lrow] = __fsub_rn(a0.x, sg[k1 + lc4 + 0]);
            As[nb][lc4 + 1][lrow] = __fsub_rn(a0.y, sg[k1 + lc4 + 1]);
            As[nb][lc4 + 2][lrow] = __fsub_rn(a0.z, sg[k1 + lc4 + 2]);
            As[nb][lc4 + 3][lrow] = __fsub_rn(a0.w, sg[k1 + lc4 + 3]);
            As[nb][lc4 + 0][64 + lrow] = __fsub_rn(a1.x, sg[k1 + lc4 + 0]);
            As[nb][lc4 + 1][64 + lrow] = __fsub_rn(a1.y, sg[k1 + lc4 + 1]);
            As[nb][lc4 + 2][64 + lrow] = __fsub_rn(a1.z, sg[k1 + lc4 + 2]);
            As[nb][lc4 + 3][64 + lrow] = __fsub_rn(a1.w, sg[k1 + lc4 + 3]);
            Bs[nb][lc4 + 0][lrow] = b0.x; Bs[nb][lc4 + 1][lrow] = b0.y;
            Bs[nb][lc4 + 2][lrow] = b0.z; Bs[nb][lc4 + 3][lrow] = b0.w;
            Bs[nb][lc4 + 0][64 + lrow] = b1.x; Bs[nb][lc4 + 1][64 + lrow] = b1.y;
            Bs[nb][lc4 + 2][64 + lrow] = b1.z; Bs[nb][lc4 + 3][64 + lrow] = b1.w;
            if (t + 2 < 16) {
                int k2 = (t + 2) * 16;
                a0 = *(const float4*)(Ap + k2);
                a1 = *(const float4*)(Ap + k2 + RO);
                b0 = *(const float4*)(Bp + k2);
                b1 = *(const float4*)(Bp + k2 + RO);
            }
        }
        #pragma unroll
        for (int kk = 0; kk < 16; kk++) {    // ascending d: in-order FMA chain
            u64x2 aL = *(const u64x2*)&As[buf][kk][ty4];
            u64x2 aH = *(const u64x2*)&As[buf][kk][64 + ty4];
            float4 bl = *(const float4*)&Bs[buf][kk][tx4];
            float4 bh = *(const float4*)&Bs[buf][kk][64 + tx4];
            ull bb[8];
            bb[0] = pk2(bl.x, bl.x); bb[1] = pk2(bl.y, bl.y);
            bb[2] = pk2(bl.z, bl.z); bb[3] = pk2(bl.w, bl.w);
            bb[4] = pk2(bh.x, bh.x); bb[5] = pk2(bh.y, bh.y);
            bb[6] = pk2(bh.z, bh.z); bb[7] = pk2(bh.w, bh.w);
            #pragma unroll
            for (int j = 0; j < 8; j++) {
                acc2[0][j] = ffma2(aL.a, bb[j], acc2[0][j]);
                acc2[1][j] = ffma2(aL.b, bb[j], acc2[1][j]);
                acc2[2][j] = ffma2(aH.a, bb[j], acc2[2][j]);
                acc2[3][j] = ffma2(aH.b, bb[j], acc2[3][j]);
            }
        }
        __syncthreads();
    }

    #pragma unroll
    for (int p = 0; p < 4; p++) {
        int rbase = (p < 2) ? (ty4 + p * 2) : (64 + ty4 + (p - 2) * 2);
        float lo[8], hi[8];
        #pragma unroll
        for (int j = 0; j < 8; j++) upk2(acc2[p][j], lo[j], hi[j]);
        #pragma unroll
        for (int h = 0; h < 2; h++) {
            int r = by * 128 + rbase + h;
            const float* src = h ? hi : lo;
            float* dst = g_S + (size_t)r * KCB + bx * 128;
            float4 v0, v1;
            v0.x = src[0]; v0.y = src[1]; v0.z = src[2]; v0.w = src[3];
            v1.x = src[4]; v1.y = src[5]; v1.z = src[6]; v1.w = src[7];
            *(float4*)(dst + tx4)      = v0;
            *(float4*)(dst + 64 + tx4) = v1;
        }
    }
}

// ---------------- shared per-token math (bit-frozen op order) ----------------
__device__ __forceinline__ float tok_rss(const float* __restrict__ Z, int n, int lane) {
    const float4* zr = (const float4*)(Z + (size_t)n * DDIM);
    const float4* gr = (const float4*)g_g;
    float rss = 0.f;
    #pragma unroll
    for (int j = 0; j < 2; j++) {
        int f = lane + j * 32;
        float4 z4 = zr[f];
        float4 g4 = gr[f];
        float r;
        r = __fsub_rn(z4.x, g4.x); rss = __fadd_rn(rss, __fmul_rn(r, r));
        r = __fsub_rn(z4.y, g4.y); rss = __fadd_rn(rss, __fmul_rn(r, r));
        r = __fsub_rn(z4.z, g4.z); rss = __fadd_rn(rss, __fmul_rn(r, r));
        r = __fsub_rn(z4.w, g4.w); rss = __fadd_rn(rss, __fmul_rn(r, r));
    }
    #pragma unroll
    for (int o = 16; o; o >>= 1) rss += __shfl_down_sync(0xffffffffu, rss, o);
    return __shfl_sync(0xffffffffu, rss, 0);
}

__device__ __forceinline__ void tok_v_argmin(int n, int l, float rss, int lane,
                                             float* v, float& best, int& bidx) {
    const float4* dotr = (const float4*)(g_S + (size_t)n * KCB);
    const float4* wssr = (const float4*)(g_wss + l * KCB);
    #pragma unroll
    for (int j = 0; j < 4; j++) {
        int f = lane + j * 32;
        float4 d4 = dotr[f];
        float4 w4 = wssr[f];
        v[j*4+0] = __fsub_rn(__fadd_rn(rss, w4.x), 2.0f * d4.x);
        v[j*4+1] = __fsub_rn(__fadd_rn(rss, w4.y), 2.0f * d4.y);
        v[j*4+2] = __fsub_rn(__fadd_rn(rss, w4.z), 2.0f * d4.z);
        v[j*4+3] = __fsub_rn(__fadd_rn(rss, w4.w), 2.0f * d4.w);
    }
    best = v[0]; bidx = lane * 4;
    #pragma unroll
    for (int j = 0; j < 4; j++)
        #pragma unroll
        for (int c = 0; c < 4; c++) {
            int k = (lane + j * 32) * 4 + c;
            float vv = v[j * 4 + c];
            if (vv < best || (vv == best && k < bidx)) { best = vv; bidx = k; }
        }
    #pragma unroll
    for (int o = 16; o; o >>= 1) {
        float ob = __shfl_down_sync(0xffffffffu, best, o);
        int   oi = __shfl_down_sync(0xffffffffu, bidx, o);
        if (ob < best || (ob == best && oi < bidx)) { best = ob; bidx = oi; }
    }
    best = __shfl_sync(0xffffffffu, best, 0);
    bidx = __shfl_sync(0xffffffffu, bidx, 0);
}

// ---------------- argmin-only (critical path): writes g_pidx + g_rss ----------------
__global__ void k_argmin(const float* __restrict__ Z, int l) {
    int tid = threadIdx.x;
    int warp = tid >> 5, lane = tid & 31;
    int n = blockIdx.x * 8 + warp;
    float rss = tok_rss(Z, n, lane);
    float v[16]; float best; int bidx;
    tok_v_argmin(n, l, rss, lane, v, best, bidx);
    if (lane == 0) {
        g_pidx[n] = bidx;
        g_rss[n]  = rss;
    }
}

// ---------------- KL + probs + indices (off critical path, forked stream) ----------
__global__ void k_klprobs(int l, float* __restrict__ out,
                          long long o_i, long long o_p) {
    int tid = threadIdx.x;
    int warp = tid >> 5, lane = tid & 31;
    int n = blockIdx.x * 8 + warp;
    float rss = g_rss[n];                 // stored: avoids racing gchain's g_g update
    float v[16]; float best; int bidx;
    tok_v_argmin(n, l, rss, lane, v, best, bidx);

    float esum = 0.f;
    float sh[16];
    #pragma unroll
    for (int j = 0; j < 16; j++) {
        sh[j] = __fsub_rn(best, v[j]);
        esum += expf(sh[j]);
    }
    #pragma unroll
    for (int o = 16; o; o >>= 1) esum += __shfl_down_sync(0xffffffffu, esum, o);
    esum = __shfl_sync(0xffffffffu, esum, 0);
    float L = logf(esum);
    float psum = 0.f;
    #pragma unroll
    for (int j = 0; j < 16; j++) psum += __fsub_rn(sh[j], L);
    #pragma unroll
    for (int o = 16; o; o >>= 1) psum += __shfl_down_sync(0xffffffffu, psum, o);

    if (o_p >= 0) {
        float* pr = out + o_p + ((size_t)n * LLV + l) * KCB;
        #pragma unroll
        for (int j = 0; j < 4; j++) {
            int f = lane + j * 32;
            float4 v4 = make_float4(0.f, 0.f, 0.f, 0.f);
            if ((bidx >> 2) == f) ((float*)&v4)[bidx & 3] = 1.0f;
            *(float4*)(pr + 4 * f) = v4;
        }
    }
    if (lane == 0) {
        float mean = psum * (1.0f / 512.0f);
        float kl = __fsub_rn(-6.238324625039508f, mean);     // -log(512) - mean
        float klw = __fmul_rn(kl, 0.1f);
        g_kl[n] = (l == 0) ? klw : __fadd_rn(g_kl[n], klw);
        g_idx[n * LLV + l] = bidx;
        if (o_i >= 0) out[o_i + (size_t)n * LLV + l] = (float)bidx;
    }
}

// ---------------- g update: per-column sequential fp32 chain (bit-identical) -------
#define GCHAIN_SMEM ((KCB + NTOK) * 4)
__global__ __launch_bounds__(256) void k_gchain(const float* __restrict__ W, int l) {
    extern __shared__ __align__(16) float dyn[];
    float* scol = dyn;            // [KCB]
    float* vbuf = dyn + KCB;      // [NTOK]
    int d = blockIdx.x;
    int tid = threadIdx.x;
    const float* Wl = W + (size_t)l * KCB * DDIM + d;

    scol[tid]       = Wl[(size_t)tid * DDIM];
    scol[tid + 256] = Wl[(size_t)(tid + 256) * DDIM];
    __syncthreads();

    #pragma unroll
    for (int j = 0; j < NTOK / 256; j++) {
        int n = tid + j * 256;
        vbuf[n] = scol[g_pidx[n]];
    }
    __syncthreads();

    if (tid == 0) {
        float part = 0.f;
        const float4* b4 = (const float4*)vbuf;
        #pragma unroll 16
        for (int j = 0; j < NTOK / 4; j++) {
            float4 q = b4[j];
            part = __fadd_rn(part, q.x);
            part = __fadd_rn(part, q.y);
            part = __fadd_rn(part, q.z);
            part = __fadd_rn(part, q.w);
        }
        g_g[d] = __fadd_rn(g_g[d], part);
    }
}

// ---------------- q_out (transposed write) + per-token loss ----------------
__global__ void k_final_q(const float* __restrict__ W, float* __restrict__ out,
                          long long o_q) {
    __shared__ int   sidx[32][8];
    __shared__ float sq[32][257];
    int tid = threadIdx.x;
    int tbase = blockIdx.x * 32;
    sidx[tid >> 3][tid & 7] = g_idx[(tbase + (tid >> 3)) * LLV + (tid & 7)];
    __syncthreads();

    int d = tid;
    for (int t = 0; t < 32; t++) {
        float acc = 0.f;
        #pragma unroll
        for (int l = 0; l < LLV; l++)
            acc = __fadd_rn(acc, W[(size_t)(l * KCB + sidx[t][l]) * DDIM + d]);
        sq[t][d] = acc;
    }
    if (tid < 32) {
        int n = tbase + tid;
        float nl = 0.f;
        float un = g_normW[sidx[tid][0]];
        #pragma unroll
        for (int l = 0; l < 7; l++) {
            float lo = g_normW[(l + 1) * KCB + sidx[tid][l + 1]];
            float r  = fmaxf(__fmul_rn(__fdiv_rn(lo, un), 4.0f), 1.0f) - 1.0f;
            nl = __fadd_rn(nl, __fmul_rn(r, r));
            un = lo;
        }
        float nlm = __fdiv_rn(nl, 7.0f);
        g_ltok[n] = __fadd_rn(g_kl[n], __fmul_rn(nlm, 0.1f));
    }
    __syncthreads();
    if (o_q >= 0) {
        int b   = tbase >> 10;
        int hw0 = tbase & 1023;
        float* dst = out + o_q + (size_t)b * (DDIM * 1024);
        for (int it = 0; it < 32; it++) {
            int e = it * 256 + tid;
            int t = e & 31;
            int dd = e >> 5;
            dst[(size_t)dd * 1024 + hw0 + t] = sq[t][dd];
        }
    }
}

// ---------------- per-batch loss mean (in-order chain, /1024 exact) ----------------
__global__ void k_final_loss(float* __restrict__ out, long long o_l) {
    int b = blockIdx.x;
    if (threadIdx.x == 0 && o_l >= 0) {
        float s = 0.f;
        for (int i = 0; i < 1024; i++) s = __fadd_rn(s, g_ltok[b * 1024 + i]);
        out[o_l + b] = s * (1.0f / 1024.0f);
    }
}

// ---------------- launch (fork klprobs onto a side stream during capture) ---------
extern "C" void kernel_launch(void* const* d_in, const int* in_sizes, int n_in,
                              void* d_out, int out_size) {
    const float* z = nullptr;
    const float* w = nullptr;
    for (int i = 0; i < n_in; i++) {
        if (in_sizes[i] == NTOK * DDIM)            z = (const float*)d_in[i];
        else if (in_sizes[i] == LLV * KCB * DDIM)  w = (const float*)d_in[i];
    }
    float* out = (float*)d_out;

    const long long SZ_Q = (long long)BATCH * DDIM * 1024;   // 4194304
    const long long SZ_I = (long long)NTOK * LLV;            // 131072
    const long long SZ_L = BATCH;                            // 16
    const long long SZ_P = (long long)NTOK * LLV * KCB;      // 67108864
    long long o_q = 0, o_i = -1, o_l = -1, o_p = -1;
    long long total = SZ_Q + SZ_I + SZ_L + SZ_P;
    if ((long long)out_size >= total) { o_i = SZ_Q; o_l = o_i + SZ_I; o_p = o_l + SZ_L; }
    else cudaMemsetAsync(d_out, 0, (size_t)out_size * sizeof(float), 0);  // fallback only

    cudaFuncSetAttribute(k_gchain, cudaFuncAttributeMaxDynamicSharedMemorySize,
                         GCHAIN_SMEM);

    cudaStream_t s2;
    cudaStreamCreateWithFlags(&s2, cudaStreamNonBlocking);
    cudaEvent_t evF[LLV], evJ[LLV];
    for (int l = 0; l < LLV; l++) {
        cudaEventCreateWithFlags(&evF[l], cudaEventDisableTiming);
        cudaEventCreateWithFlags(&evJ[l], cudaEventDisableTiming);
    }

    k_init<<<16, 256>>>(w);
    for (int l = 0; l < LLV; l++) {
        k_gemm<<<dim3(4, 128), 256>>>(z, w + (size_t)l * KCB * DDIM);
        k_argmin<<<2048, 256>>>(z, l);
        cudaEventRecord(evF[l], 0);
        cudaStreamWaitEvent(s2, evF[l], 0);
        k_klprobs<<<2048, 256, 0, s2>>>(l, out, o_i, o_p);   // runs under gchain
        if (l < LLV - 1) k_gchain<<<DDIM, 256, GCHAIN_SMEM>>>(w, l);
        cudaEventRecord(evJ[l], s2);
        cudaStreamWaitEvent(0, evJ[l], 0);   // klprobs reads g_S before next gemm
    }
    k_final_q<<<512, 256>>>(w, out, o_q);
    k_final_loss<<<BATCH, 256>>>(out, o_l);

    // release per-call objects (not captured; safe after all launches recorded)
    for (int l = 0; l < LLV; l++) { cudaEventDestroy(evF[l]); cudaEventDestroy(evJ[l]); }
    cudaStreamDestroy(s2);
}

// round 13
// speedup vs baseline: 1.0128x; 1.0128x over previous
#include <cuda_runtime.h>
#include <math.h>

#define NTOK 16384
#define DDIM 256
#define KCB  512
#define LLV  8
#define BATCH 16

// ---------------- device scratch (static, no allocations) ----------------
__device__ float g_S[NTOK * KCB];      // raw dot[n,k] for current level (32 MB)
__device__ float g_g[DDIM];            // global_sum, fp32, reference-exact chain
__device__ float g_wss[LLV * KCB];     // ||W_k||^2
__device__ float g_normW[LLV * KCB];   // ||W_k||
__device__ float g_kl[NTOK];           // kl accumulator
__device__ int   g_idx[NTOK * LLV];    // picks (strided by level)
__device__ int   g_pidx[NTOK];         // packed picks for current level
__device__ float g_ltok[NTOK];         // per-token loss

typedef unsigned long long ull;
struct __align__(16) u64x2 { ull a, b; };

__device__ __forceinline__ ull pk2(float lo, float hi) {
    ull r;
    asm("mov.b64 %0, {%1, %2};" : "=l"(r) : "f"(lo), "f"(hi));
    return r;
}
__device__ __forceinline__ void upk2(ull v, float& lo, float& hi) {
    asm("mov.b64 {%0, %1}, %2;" : "=f"(lo), "=f"(hi) : "l"(v));
}
__device__ __forceinline__ ull ffma2(ull a, ull b, ull c) {
    ull d;
    asm("fma.rn.f32x2 %0, %1, %2, %3;" : "=l"(d) : "l"(a), "l"(b), "l"(c));
    return d;
}

// ---------------- init: wss, norms, zero g ----------------
__global__ void k_init(const float* __restrict__ W) {
    int gid = blockIdx.x * blockDim.x + threadIdx.x;   // 16*256 = 4096
    if (gid < LLV * KCB) {
        const float4* row = (const float4*)(W + (size_t)gid * DDIM);
        float acc = 0.f;
        #pragma unroll 8
        for (int j = 0; j < DDIM / 4; j++) {
            float4 w4 = row[j];
            acc = __fadd_rn(acc, __fmul_rn(w4.x, w4.x));
            acc = __fadd_rn(acc, __fmul_rn(w4.y, w4.y));
            acc = __fadd_rn(acc, __fmul_rn(w4.z, w4.z));
            acc = __fadd_rn(acc, __fmul_rn(w4.w, w4.w));
        }
        g_wss[gid]   = acc;
        g_normW[gid] = sqrtf(acc);
    }
    if (gid < DDIM) g_g[gid] = 0.f;
}

// ---------------- GEMM (bit-frozen, round-10 verbatim): 128x128 tile, BK=16 -------
__global__ __launch_bounds__(256, 2) void k_gemm(const float* __restrict__ Z,
                                                 const float* __restrict__ W) {
    __shared__ __align__(16) float As[2][16][132];
    __shared__ __align__(16) float Bs[2][16][132];
    __shared__ float sg[DDIM];
    int tid = threadIdx.x;
    int bx = blockIdx.x, by = blockIdx.y;   // bx 0..3, by 0..127
    int tx = tid & 15, ty = tid >> 4;
    int ty4 = ty * 4, tx4 = tx * 4;
    int lrow = tid >> 2;                    // 0..63
    int lc4  = (tid & 3) * 4;               // 0,4,8,12
    const int RO = 64 * DDIM;               // +64 rows
    const float* Ap = Z + (size_t)(by * 128 + lrow) * DDIM + lc4;
    const float* Bp = W + (size_t)(bx * 128 + lrow) * DDIM + lc4;

    sg[tid] = g_g[tid];

    ull acc2[4][8];   // row-pairs x 8 cols
    #pragma unroll
    for (int p = 0; p < 4; p++)
        #pragma unroll
        for (int j = 0; j < 8; j++) acc2[p][j] = 0ull;

    float4 a0 = *(const float4*)Ap;
    float4 a1 = *(const float4*)(Ap + RO);
    float4 b0 = *(const float4*)Bp;
    float4 b1 = *(const float4*)(Bp + RO);
    __syncthreads();                          // sg visible

    {
        As[0][lc4 + 0][lrow] = __fsub_rn(a0.x, sg[lc4 + 0]);
        As[0][lc4 + 1][lrow] = __fsub_rn(a0.y, sg[lc4 + 1]);
        As[0][lc4 + 2][lrow] = __fsub_rn(a0.z, sg[lc4 + 2]);
        As[0][lc4 + 3][lrow] = __fsub_rn(a0.w, sg[lc4 + 3]);
        As[0][lc4 + 0][64 + lrow] = __fsub_rn(a1.x, sg[lc4 + 0]);
        As[0][lc4 + 1][64 + lrow] = __fsub_rn(a1.y, sg[lc4 + 1]);
        As[0][lc4 + 2][64 + lrow] = __fsub_rn(a1.z, sg[lc4 + 2]);
        As[0][lc4 + 3][64 + lrow] = __fsub_rn(a1.w, sg[lc4 + 3]);
        Bs[0][lc4 + 0][lrow] = b0.x; Bs[0][lc4 + 1][lrow] = b0.y;
        Bs[0][lc4 + 2][lrow] = b0.z; Bs[0][lc4 + 3][lrow] = b0.w;
        Bs[0][lc4 + 0][64 + lrow] = b1.x; Bs[0][lc4 + 1][64 + lrow] = b1.y;
        Bs[0][lc4 + 2][64 + lrow] = b1.z; Bs[0][lc4 + 3][64 + lrow] = b1.w;
    }
    a0 = *(const float4*)(Ap + 16);          // prefetch tile 1
    a1 = *(const float4*)(Ap + 16 + RO);
    b0 = *(const float4*)(Bp + 16);
    b1 = *(const float4*)(Bp + 16 + RO);
    __syncthreads();

    for (int t = 0; t < 16; t++) {
        int buf = t & 1;
        if (t + 1 < 16) {
            int nb = (t + 1) & 1;
            int k1 = (t + 1) * 16;
            As[nb][lc4 + 0][lrow] = __fsub_rn(a0.x, sg[k1 + lc4 + 0]);
            As[nb][lc4 + 1][lrow] = __fsub_rn(a0.y, sg[k1 + lc4 + 1]);
            As[nb][lc4 + 2][lrow] = __fsub_rn(a0.z, sg[k1 + lc4 + 2]);
            As[nb][lc4 + 3][lrow] = __fsub_rn(a0.w, sg[k1 + lc4 + 3]);
            As[nb][lc4 + 0][64 + lrow] = __fsub_rn(a1.x, sg[k1 + lc4 + 0]);
            As[nb][lc4 + 1][64 + lrow] = __fsub_rn(a1.y, sg[k1 + lc4 + 1]);
            As[nb][lc4 + 2][64 + lrow] = __fsub_rn(a1.z, sg[k1 + lc4 + 2]);
            As[nb][lc4 + 3][64 + lrow] = __fsub_rn(a1.w, sg[k1 + lc4 + 3]);
            Bs[nb][lc4 + 0][lrow] = b0.x; Bs[nb][lc4 + 1][lrow] = b0.y;
            Bs[nb][lc4 + 2][lrow] = b0.z; Bs[nb][lc4 + 3][lrow] = b0.w;
            Bs[nb][lc4 + 0][64 + lrow] = b1.x; Bs[nb][lc4 + 1][64 + lrow] = b1.y;
            Bs[nb][lc4 + 2][64 + lrow] = b1.z; Bs[nb][lc4 + 3][64 + lrow] = b1.w;
            if (t + 2 < 16) {
                int k2 = (t + 2) * 16;
                a0 = *(const float4*)(Ap + k2);
                a1 = *(const float4*)(Ap + k2 + RO);
                b0 = *(const float4*)(Bp + k2);
                b1 = *(const float4*)(Bp + k2 + RO);
            }
        }
        #pragma unroll
        for (int kk = 0; kk < 16; kk++) {    // ascending d: in-order FMA chain
            u64x2 aL = *(const u64x2*)&As[buf][kk][ty4];
            u64x2 aH = *(const u64x2*)&As[buf][kk][64 + ty4];
            float4 bl = *(const float4*)&Bs[buf][kk][tx4];
            float4 bh = *(const float4*)&Bs[buf][kk][64 + tx4];
            ull bb[8];
            bb[0] = pk2(bl.x, bl.x); bb[1] = pk2(bl.y, bl.y);
            bb[2] = pk2(bl.z, bl.z); bb[3] = pk2(bl.w, bl.w);
            bb[4] = pk2(bh.x, bh.x); bb[5] = pk2(bh.y, bh.y);
            bb[6] = pk2(bh.z, bh.z); bb[7] = pk2(bh.w, bh.w);
            #pragma unroll
            for (int j = 0; j < 8; j++) {
                acc2[0][j] = ffma2(aL.a, bb[j], acc2[0][j]);
                acc2[1][j] = ffma2(aL.b, bb[j], acc2[1][j]);
                acc2[2][j] = ffma2(aH.a, bb[j], acc2[2][j]);
                acc2[3][j] = ffma2(aH.b, bb[j], acc2[3][j]);
            }
        }
        __syncthreads();
    }

    #pragma unroll
    for (int p = 0; p < 4; p++) {
        int rbase = (p < 2) ? (ty4 + p * 2) : (64 + ty4 + (p - 2) * 2);
        float lo[8], hi[8];
        #pragma unroll
        for (int j = 0; j < 8; j++) upk2(acc2[p][j], lo[j], hi[j]);
        #pragma unroll
        for (int h = 0; h < 2; h++) {
            int r = by * 128 + rbase + h;
            const float* src = h ? hi : lo;
            float* dst = g_S + (size_t)r * KCB + bx * 128;
            float4 v0, v1;
            v0.x = src[0]; v0.y = src[1]; v0.z = src[2]; v0.w = src[3];
            v1.x = src[4]; v1.y = src[5]; v1.z = src[6]; v1.w = src[7];
            *(float4*)(dst + tx4)      = v0;
            *(float4*)(dst + 64 + tx4) = v1;
        }
    }
}

// ---------------- per-token reduce, 2 tokens per warp (bit-frozen per-token ops) ---
__global__ void k_reduce(const float* __restrict__ Z, int l, float* __restrict__ out,
                         long long o_i, long long o_p) {
    int tid = threadIdx.x;
    int warp = tid >> 5, lane = tid & 31;
    int n0 = blockIdx.x * 16 + warp * 2;     // tokens n0, n0+1

    const float4* gr = (const float4*)g_g;
    float4 gc[2];
    gc[0] = gr[lane];
    gc[1] = gr[lane + 32];

    float rssA = 0.f, rssB = 0.f;
    {
        const float4* zrA = (const float4*)(Z + (size_t)n0 * DDIM);
        const float4* zrB = (const float4*)(Z + (size_t)(n0 + 1) * DDIM);
        float4 zA0 = zrA[lane], zA1 = zrA[lane + 32];
        float4 zB0 = zrB[lane], zB1 = zrB[lane + 32];
        float r;
        // token A, in frozen order (j=0 then j=1)
        r = __fsub_rn(zA0.x, gc[0].x); rssA = __fadd_rn(rssA, __fmul_rn(r, r));
        r = __fsub_rn(zA0.y, gc[0].y); rssA = __fadd_rn(rssA, __fmul_rn(r, r));
        r = __fsub_rn(zA0.z, gc[0].z); rssA = __fadd_rn(rssA, __fmul_rn(r, r));
        r = __fsub_rn(zA0.w, gc[0].w); rssA = __fadd_rn(rssA, __fmul_rn(r, r));
        r = __fsub_rn(zA1.x, gc[1].x); rssA = __fadd_rn(rssA, __fmul_rn(r, r));
        r = __fsub_rn(zA1.y, gc[1].y); rssA = __fadd_rn(rssA, __fmul_rn(r, r));
        r = __fsub_rn(zA1.z, gc[1].z); rssA = __fadd_rn(rssA, __fmul_rn(r, r));
        r = __fsub_rn(zA1.w, gc[1].w); rssA = __fadd_rn(rssA, __fmul_rn(r, r));
        // token B, same order
        r = __fsub_rn(zB0.x, gc[0].x); rssB = __fadd_rn(rssB, __fmul_rn(r, r));
        r = __fsub_rn(zB0.y, gc[0].y); rssB = __fadd_rn(rssB, __fmul_rn(r, r));
        r = __fsub_rn(zB0.z, gc[0].z); rssB = __fadd_rn(rssB, __fmul_rn(r, r));
        r = __fsub_rn(zB0.w, gc[0].w); rssB = __fadd_rn(rssB, __fmul_rn(r, r));
        r = __fsub_rn(zB1.x, gc[1].x); rssB = __fadd_rn(rssB, __fmul_rn(r, r));
        r = __fsub_rn(zB1.y, gc[1].y); rssB = __fadd_rn(rssB, __fmul_rn(r, r));
        r = __fsub_rn(zB1.z, gc[1].z); rssB = __fadd_rn(rssB, __fmul_rn(r, r));
        r = __fsub_rn(zB1.w, gc[1].w); rssB = __fadd_rn(rssB, __fmul_rn(r, r));
    }
    #pragma unroll
    for (int o = 16; o; o >>= 1) {
        rssA += __shfl_down_sync(0xffffffffu, rssA, o);
        rssB += __shfl_down_sync(0xffffffffu, rssB, o);
    }
    rssA = __shfl_sync(0xffffffffu, rssA, 0);
    rssB = __shfl_sync(0xffffffffu, rssB, 0);

    const float4* dotA = (const float4*)(g_S + (size_t)n0 * KCB);
    const float4* dotB = (const float4*)(g_S + (size_t)(n0 + 1) * KCB);
    const float4* wssr = (const float4*)(g_wss + l * KCB);

    float vA[16], vB[16];
    #pragma unroll
    for (int j = 0; j < 4; j++) {
        int f = lane + j * 32;
        float4 dA = dotA[f];
        float4 dB = dotB[f];
        float4 w4 = wssr[f];
        vA[j*4+0] = __fsub_rn(__fadd_rn(rssA, w4.x), 2.0f * dA.x);
        vA[j*4+1] = __fsub_rn(__fadd_rn(rssA, w4.y), 2.0f * dA.y);
        vA[j*4+2] = __fsub_rn(__fadd_rn(rssA, w4.z), 2.0f * dA.z);
        vA[j*4+3] = __fsub_rn(__fadd_rn(rssA, w4.w), 2.0f * dA.w);
        vB[j*4+0] = __fsub_rn(__fadd_rn(rssB, w4.x), 2.0f * dB.x);
        vB[j*4+1] = __fsub_rn(__fadd_rn(rssB, w4.y), 2.0f * dB.y);
        vB[j*4+2] = __fsub_rn(__fadd_rn(rssB, w4.z), 2.0f * dB.z);
        vB[j*4+3] = __fsub_rn(__fadd_rn(rssB, w4.w), 2.0f * dB.w);
    }
    float bestA = vA[0]; int bidxA = lane * 4;
    float bestB = vB[0]; int bidxB = lane * 4;
    #pragma unroll
    for (int j = 0; j < 4; j++)
        #pragma unroll
        for (int c = 0; c < 4; c++) {
            int k = (lane + j * 32) * 4 + c;
            float va = vA[j * 4 + c];
            if (va < bestA || (va == bestA && k < bidxA)) { bestA = va; bidxA = k; }
            float vb = vB[j * 4 + c];
            if (vb < bestB || (vb == bestB && k < bidxB)) { bestB = vb; bidxB = k; }
        }
    #pragma unroll
    for (int o = 16; o; o >>= 1) {
        float oa = __shfl_down_sync(0xffffffffu, bestA, o);
        int   ia = __shfl_down_sync(0xffffffffu, bidxA, o);
        if (oa < bestA || (oa == bestA && ia < bidxA)) { bestA = oa; bidxA = ia; }
        float ob = __shfl_down_sync(0xffffffffu, bestB, o);
        int   ib = __shfl_down_sync(0xffffffffu, bidxB, o);
        if (ob < bestB || (ob == bestB && ib < bidxB)) { bestB = ob; bidxB = ib; }
    }
    bestA = __shfl_sync(0xffffffffu, bestA, 0);
    bidxA = __shfl_sync(0xffffffffu, bidxA, 0);
    bestB = __shfl_sync(0xffffffffu, bestB, 0);
    bidxB = __shfl_sync(0xffffffffu, bidxB, 0);

    float esumA = 0.f, esumB = 0.f;
    float shA[16], shB[16];
    #pragma unroll
    for (int j = 0; j < 16; j++) {
        shA[j] = __fsub_rn(bestA, vA[j]);
        esumA += expf(shA[j]);
        shB[j] = __fsub_rn(bestB, vB[j]);
        esumB += expf(shB[j]);
    }
    #pragma unroll
    for (int o = 16; o; o >>= 1) {
        esumA += __shfl_down_sync(0xffffffffu, esumA, o);
        esumB += __shfl_down_sync(0xffffffffu, esumB, o);
    }
    esumA = __shfl_sync(0xffffffffu, esumA, 0);
    esumB = __shfl_sync(0xffffffffu, esumB, 0);
    float LA = logf(esumA);
    float LB = logf(esumB);
    float psumA = 0.f, psumB = 0.f;
    #pragma unroll
    for (int j = 0; j < 16; j++) {
        psumA += __fsub_rn(shA[j], LA);
        psumB += __fsub_rn(shB[j], LB);
    }
    #pragma unroll
    for (int o = 16; o; o >>= 1) {
        psumA += __shfl_down_sync(0xffffffffu, psumA, o);
        psumB += __shfl_down_sync(0xffffffffu, psumB, o);
    }

    // fused one-hot probs rows
    if (o_p >= 0) {
        float* prA = out + o_p + ((size_t)n0 * LLV + l) * KCB;
        float* prB = out + o_p + ((size_t)(n0 + 1) * LLV + l) * KCB;
        #pragma unroll
        for (int j = 0; j < 4; j++) {
            int f = lane + j * 32;
            float4 v4 = make_float4(0.f, 0.f, 0.f, 0.f);
            if ((bidxA >> 2) == f) ((float*)&v4)[bidxA & 3] = 1.0f;
            *(float4*)(prA + 4 * f) = v4;
            float4 w4 = make_float4(0.f, 0.f, 0.f, 0.f);
            if ((bidxB >> 2) == f) ((float*)&w4)[bidxB & 3] = 1.0f;
            *(float4*)(prB + 4 * f) = w4;
        }
    }

    if (lane == 0) {
        float meanA = psumA * (1.0f / 512.0f);
        float klA = __fsub_rn(-6.238324625039508f, meanA);
        float klwA = __fmul_rn(klA, 0.1f);
        g_kl[n0] = (l == 0) ? klwA : __fadd_rn(g_kl[n0], klwA);
        g_idx[n0 * LLV + l] = bidxA;
        g_pidx[n0] = bidxA;
        float meanB = psumB * (1.0f / 512.0f);
        float klB = __fsub_rn(-6.238324625039508f, meanB);
        float klwB = __fmul_rn(klB, 0.1f);
        g_kl[n0 + 1] = (l == 0) ? klwB : __fadd_rn(g_kl[n0 + 1], klwB);
        g_idx[(n0 + 1) * LLV + l] = bidxB;
        g_pidx[n0 + 1] = bidxB;
        if (o_i >= 0) {
            out[o_i + (size_t)n0 * LLV + l] = (float)bidxA;
            out[o_i + (size_t)(n0 + 1) * LLV + l] = (float)bidxB;
        }
    }
}

// ---------------- g update: per-column sequential fp32 chain (bit-identical) -------
#define GCHAIN_SMEM ((KCB + NTOK) * 4)
__global__ __launch_bounds__(256) void k_gchain(const float* __restrict__ W, int l) {
    extern __shared__ __align__(16) float dyn[];
    float* scol = dyn;            // [KCB]
    float* vbuf = dyn + KCB;      // [NTOK]
    int d = blockIdx.x;
    int tid = threadIdx.x;
    const float* Wl = W + (size_t)l * KCB * DDIM + d;

    scol[tid]       = Wl[(size_t)tid * DDIM];
    scol[tid + 256] = Wl[(size_t)(tid + 256) * DDIM];
    __syncthreads();

    #pragma unroll
    for (int j = 0; j < NTOK / 256; j++) {
        int n = tid + j * 256;
        vbuf[n] = scol[g_pidx[n]];
    }
    __syncthreads();

    if (tid == 0) {
        float part = 0.f;
        const float4* b4 = (const float4*)vbuf;
        #pragma unroll 16
        for (int j = 0; j < NTOK / 4; j++) {
            float4 q = b4[j];
            part = __fadd_rn(part, q.x);
            part = __fadd_rn(part, q.y);
            part = __fadd_rn(part, q.z);
            part = __fadd_rn(part, q.w);
        }
        g_g[d] = __fadd_rn(g_g[d], part);
    }
}

// ---------------- q_out (transposed write) + per-token loss ----------------
__global__ void k_final_q(const float* __restrict__ W, float* __restrict__ out,
                          long long o_q) {
    __shared__ int   sidx[32][8];
    __shared__ float sq[32][257];
    int tid = threadIdx.x;
    int tbase = blockIdx.x * 32;
    sidx[tid >> 3][tid & 7] = g_idx[(tbase + (tid >> 3)) * LLV + (tid & 7)];
    __syncthreads();

    int d = tid;
    for (int t = 0; t < 32; t++) {
        float acc = 0.f;
        #pragma unroll
        for (int l = 0; l < LLV; l++)
            acc = __fadd_rn(acc, W[(size_t)(l * KCB + sidx[t][l]) * DDIM + d]);
        sq[t][d] = acc;
    }
    if (tid < 32) {
        int n = tbase + tid;
        float nl = 0.f;
        float un = g_normW[sidx[tid][0]];
        #pragma unroll
        for (int l = 0; l < 7; l++) {
            float lo = g_normW[(l + 1) * KCB + sidx[tid][l + 1]];
            float r  = fmaxf(__fmul_rn(__fdiv_rn(lo, un), 4.0f), 1.0f) - 1.0f;
            nl = __fadd_rn(nl, __fmul_rn(r, r));
            un = lo;
        }
        float nlm = __fdiv_rn(nl, 7.0f);
        g_ltok[n] = __fadd_rn(g_kl[n], __fmul_rn(nlm, 0.1f));
    }
    __syncthreads();
    if (o_q >= 0) {
        int b   = tbase >> 10;
        int hw0 = tbase & 1023;
        float* dst = out + o_q + (size_t)b * (DDIM * 1024);
        for (int it = 0; it < 32; it++) {
            int e = it * 256 + tid;
            int t = e & 31;
            int dd = e >> 5;
            dst[(size_t)dd * 1024 + hw0 + t] = sq[t][dd];
        }
    }
}

// ---------------- per-batch loss mean (in-order chain, /1024 exact) ----------------
__global__ void k_final_loss(float* __restrict__ out, long long o_l) {
    int b = blockIdx.x;
    if (threadIdx.x == 0 && o_l >= 0) {
        float s = 0.f;
        for (int i = 0; i < 1024; i++) s = __fadd_rn(s, g_ltok[b * 1024 + i]);
        out[o_l + b] = s * (1.0f / 1024.0f);
    }
}

// ---------------- launch ----------------
extern "C" void kernel_launch(void* const* d_in, const int* in_sizes, int n_in,
                              void* d_out, int out_size) {
    const float* z = nullptr;
    const float* w = nullptr;
    for (int i = 0; i < n_in; i++) {
        if (in_sizes[i] == NTOK * DDIM)            z = (const float*)d_in[i];
        else if (in_sizes[i] == LLV * KCB * DDIM)  w = (const float*)d_in[i];
    }
    float* out = (float*)d_out;

    const long long SZ_Q = (long long)BATCH * DDIM * 1024;   // 4194304
    const long long SZ_I = (long long)NTOK * LLV;            // 131072
    const long long SZ_L = BATCH;                            // 16
    const long long SZ_P = (long long)NTOK * LLV * KCB;      // 67108864
    long long o_q = 0, o_i = -1, o_l = -1, o_p = -1;
    long long total = SZ_Q + SZ_I + SZ_L + SZ_P;
    if ((long long)out_size >= total) { o_i = SZ_Q; o_l = o_i + SZ_I; o_p = o_l + SZ_L; }
    else cudaMemsetAsync(d_out, 0, (size_t)out_size * sizeof(float), 0);  // fallback only

    cudaFuncSetAttribute(k_gchain, cudaFuncAttributeMaxDynamicSharedMemorySize,
                         GCHAIN_SMEM);

    k_init<<<16, 256>>>(w);
    for (int l = 0; l < LLV; l++) {
        k_gemm<<<dim3(4, 128), 256>>>(z, w + (size_t)l * KCB * DDIM);
        k_reduce<<<1024, 256>>>(z, l, out, o_i, o_p);
        if (l < LLV - 1) k_gchain<<<DDIM, 256, GCHAIN_SMEM>>>(w, l);
    }
    k_final_q<<<512, 256>>>(w, out, o_q);
    k_final_loss<<<BATCH, 256>>>(out, o_l);
}

// round 14
// speedup vs baseline: 1.0474x; 1.0342x over previous
#include <cuda_runtime.h>
#include <math.h>

#define NTOK 16384
#define DDIM 256
#define KCB  512
#define LLV  8
#define BATCH 16

// ---------------- device scratch (static, no allocations) ----------------
__device__ float g_S[NTOK * KCB];      // raw dot[n,k] for current level (32 MB)
__device__ float g_g[DDIM];            // global_sum, fp32, reference-exact chain
__device__ float g_wss[LLV * KCB];     // ||W_k||^2
__device__ float g_normW[LLV * KCB];   // ||W_k||
__device__ float g_kl[NTOK];           // kl accumulator
__device__ int   g_idx[NTOK * LLV];    // picks (strided by level)
__device__ int   g_pidx[NTOK];         // packed picks for current level
__device__ float g_ltok[NTOK];         // per-token loss

typedef unsigned long long ull;
struct __align__(16) u64x2 { ull a, b; };

__device__ __forceinline__ ull pk2(float lo, float hi) {
    ull r;
    asm("mov.b64 %0, {%1, %2};" : "=l"(r) : "f"(lo), "f"(hi));
    return r;
}
__device__ __forceinline__ void upk2(ull v, float& lo, float& hi) {
    asm("mov.b64 {%0, %1}, %2;" : "=f"(lo), "=f"(hi) : "l"(v));
}
__device__ __forceinline__ ull ffma2(ull a, ull b, ull c) {
    ull d;
    asm("fma.rn.f32x2 %0, %1, %2, %3;" : "=l"(d) : "l"(a), "l"(b), "l"(c));
    return d;
}

// ---------------- init: wss, norms, zero g ----------------
__global__ void k_init(const float* __restrict__ W) {
    int gid = blockIdx.x * blockDim.x + threadIdx.x;   // 16*256 = 4096
    if (gid < LLV * KCB) {
        const float4* row = (const float4*)(W + (size_t)gid * DDIM);
        float acc = 0.f;
        #pragma unroll 8
        for (int j = 0; j < DDIM / 4; j++) {
            float4 w4 = row[j];
            acc = __fadd_rn(acc, __fmul_rn(w4.x, w4.x));
            acc = __fadd_rn(acc, __fmul_rn(w4.y, w4.y));
            acc = __fadd_rn(acc, __fmul_rn(w4.z, w4.z));
            acc = __fadd_rn(acc, __fmul_rn(w4.w, w4.w));
        }
        g_wss[gid]   = acc;
        g_normW[gid] = sqrtf(acc);
    }
    if (gid < DDIM) g_g[gid] = 0.f;
}

// ---------------- GEMM (bit-frozen, round-10 verbatim): 128x128 tile, BK=16 -------
__global__ __launch_bounds__(256, 2) void k_gemm(const float* __restrict__ Z,
                                                 const float* __restrict__ W) {
    __shared__ __align__(16) float As[2][16][132];
    __shared__ __align__(16) float Bs[2][16][132];
    __shared__ float sg[DDIM];
    int tid = threadIdx.x;
    int bx = blockIdx.x, by = blockIdx.y;   // bx 0..3, by 0..127
    int tx = tid & 15, ty = tid >> 4;
    int ty4 = ty * 4, tx4 = tx * 4;
    int lrow = tid >> 2;                    // 0..63
    int lc4  = (tid & 3) * 4;               // 0,4,8,12
    const int RO = 64 * DDIM;               // +64 rows
    const float* Ap = Z + (size_t)(by * 128 + lrow) * DDIM + lc4;
    const float* Bp = W + (size_t)(bx * 128 + lrow) * DDIM + lc4;

    sg[tid] = g_g[tid];

    ull acc2[4][8];   // row-pairs x 8 cols
    #pragma unroll
    for (int p = 0; p < 4; p++)
        #pragma unroll
        for (int j = 0; j < 8; j++) acc2[p][j] = 0ull;

    float4 a0 = *(const float4*)Ap;
    float4 a1 = *(const float4*)(Ap + RO);
    float4 b0 = *(const float4*)Bp;
    float4 b1 = *(const float4*)(Bp + RO);
    __syncthreads();                          // sg visible

    {
        As[0][lc4 + 0][lrow] = __fsub_rn(a0.x, sg[lc4 + 0]);
        As[0][lc4 + 1][lrow] = __fsub_rn(a0.y, sg[lc4 + 1]);
        As[0][lc4 + 2][lrow] = __fsub_rn(a0.z, sg[lc4 + 2]);
        As[0][lc4 + 3][lrow] = __fsub_rn(a0.w, sg[lc4 + 3]);
        As[0][lc4 + 0][64 + lrow] = __fsub_rn(a1.x, sg[lc4 + 0]);
        As[0][lc4 + 1][64 + lrow] = __fsub_rn(a1.y, sg[lc4 + 1]);
        As[0][lc4 + 2][64 + lrow] = __fsub_rn(a1.z, sg[lc4 + 2]);
        As[0][lc4 + 3][64 + lrow] = __fsub_rn(a1.w, sg[lc4 + 3]);
        Bs[0][lc4 + 0][lrow] = b0.x; Bs[0][lc4 + 1][lrow] = b0.y;
        Bs[0][lc4 + 2][lrow] = b0.z; Bs[0][lc4 + 3][lrow] = b0.w;
        Bs[0][lc4 + 0][64 + lrow] = b1.x; Bs[0][lc4 + 1][64 + lrow] = b1.y;
        Bs[0][lc4 + 2][64 + lrow] = b1.z; Bs[0][lc4 + 3][64 + lrow] = b1.w;
    }
    a0 = *(const float4*)(Ap + 16);          // prefetch tile 1
    a1 = *(const float4*)(Ap + 16 + RO);
    b0 = *(const float4*)(Bp + 16);
    b1 = *(const float4*)(Bp + 16 + RO);
    __syncthreads();

    for (int t = 0; t < 16; t++) {
        int buf = t & 1;
        if (t + 1 < 16) {
            int nb = (t + 1) & 1;
            int k1 = (t + 1) * 16;
            As[nb][lc4 + 0][lrow] = __fsub_rn(a0.x, sg[k1 + lc4 + 0]);
            As[nb][lc4 + 1][lrow] = __fsub_rn(a0.y, sg[k1 + lc4 + 1]);
            As[nb][lc4 + 2][lrow] = __fsub_rn(a0.z, sg[k1 + lc4 + 2]);
            As[nb][lc4 + 3][lrow] = __fsub_rn(a0.w, sg[k1 + lc4 + 3]);
            As[nb][lc4 + 0][64 + lrow] = __fsub_rn(a1.x, sg[k1 + lc4 + 0]);
            As[nb][lc4 + 1][64 + lrow] = __fsub_rn(a1.y, sg[k1 + lc4 + 1]);
            As[nb][lc4 + 2][64 + lrow] = __fsub_rn(a1.z, sg[k1 + lc4 + 2]);
            As[nb][lc4 + 3][64 + lrow] = __fsub_rn(a1.w, sg[k1 + lc4 + 3]);
            Bs[nb][lc4 + 0][lrow] = b0.x; Bs[nb][lc4 + 1][lrow] = b0.y;
            Bs[nb][lc4 + 2][lrow] = b0.z; Bs[nb][lc4 + 3][lrow] = b0.w;
            Bs[nb][lc4 + 0][64 + lrow] = b1.x; Bs[nb][lc4 + 1][64 + lrow] = b1.y;
            Bs[nb][lc4 + 2][64 + lrow] = b1.z; Bs[nb][lc4 + 3][64 + lrow] = b1.w;
            if (t + 2 < 16) {
                int k2 = (t + 2) * 16;
                a0 = *(const float4*)(Ap + k2);
                a1 = *(const float4*)(Ap + k2 + RO);
                b0 = *(const float4*)(Bp + k2);
                b1 = *(const float4*)(Bp + k2 + RO);
            }
        }
        #pragma unroll
        for (int kk = 0; kk < 16; kk++) {    // ascending d: in-order FMA chain
            u64x2 aL = *(const u64x2*)&As[buf][kk][ty4];
            u64x2 aH = *(const u64x2*)&As[buf][kk][64 + ty4];
            float4 bl = *(const float4*)&Bs[buf][kk][tx4];
            float4 bh = *(const float4*)&Bs[buf][kk][64 + tx4];
            ull bb[8];
            bb[0] = pk2(bl.x, bl.x); bb[1] = pk2(bl.y, bl.y);
            bb[2] = pk2(bl.z, bl.z); bb[3] = pk2(bl.w, bl.w);
            bb[4] = pk2(bh.x, bh.x); bb[5] = pk2(bh.y, bh.y);
            bb[6] = pk2(bh.z, bh.z); bb[7] = pk2(bh.w, bh.w);
            #pragma unroll
            for (int j = 0; j < 8; j++) {
                acc2[0][j] = ffma2(aL.a, bb[j], acc2[0][j]);
                acc2[1][j] = ffma2(aL.b, bb[j], acc2[1][j]);
                acc2[2][j] = ffma2(aH.a, bb[j], acc2[2][j]);
                acc2[3][j] = ffma2(aH.b, bb[j], acc2[3][j]);
            }
        }
        __syncthreads();
    }

    #pragma unroll
    for (int p = 0; p < 4; p++) {
        int rbase = (p < 2) ? (ty4 + p * 2) : (64 + ty4 + (p - 2) * 2);
        float lo[8], hi[8];
        #pragma unroll
        for (int j = 0; j < 8; j++) upk2(acc2[p][j], lo[j], hi[j]);
        #pragma unroll
        for (int h = 0; h < 2; h++) {
            int r = by * 128 + rbase + h;
            const float* src = h ? hi : lo;
            float* dst = g_S + (size_t)r * KCB + bx * 128;
            float4 v0, v1;
            v0.x = src[0]; v0.y = src[1]; v0.z = src[2]; v0.w = src[3];
            v1.x = src[4]; v1.y = src[5]; v1.z = src[6]; v1.w = src[7];
            *(float4*)(dst + tx4)      = v0;
            *(float4*)(dst + 64 + tx4) = v1;
        }
    }
}

// ---------------- per-token: rss fused + m_k + argmin + KL (bit-frozen) + fused
// one-hot probs row + float index writes (round-10 verbatim) ----------------
__global__ void k_reduce(const float* __restrict__ Z, int l, float* __restrict__ out,
                         long long o_i, long long o_p) {
    int tid = threadIdx.x;
    int warp = tid >> 5, lane = tid & 31;
    int n = blockIdx.x * 8 + warp;

    const float4* zr = (const float4*)(Z + (size_t)n * DDIM);
    const float4* gr = (const float4*)g_g;
    float rss = 0.f;
    #pragma unroll
    for (int j = 0; j < 2; j++) {
        int f = lane + j * 32;
        float4 z4 = zr[f];
        float4 g4 = gr[f];
        float r;
        r = __fsub_rn(z4.x, g4.x); rss = __fadd_rn(rss, __fmul_rn(r, r));
        r = __fsub_rn(z4.y, g4.y); rss = __fadd_rn(rss, __fmul_rn(r, r));
        r = __fsub_rn(z4.z, g4.z); rss = __fadd_rn(rss, __fmul_rn(r, r));
        r = __fsub_rn(z4.w, g4.w); rss = __fadd_rn(rss, __fmul_rn(r, r));
    }
    #pragma unroll
    for (int o = 16; o; o >>= 1) rss += __shfl_down_sync(0xffffffffu, rss, o);
    rss = __shfl_sync(0xffffffffu, rss, 0);

    const float4* dotr = (const float4*)(g_S + (size_t)n * KCB);
    const float4* wssr = (const float4*)(g_wss + l * KCB);

    float v[16];
    #pragma unroll
    for (int j = 0; j < 4; j++) {
        int f = lane + j * 32;
        float4 d4 = dotr[f];
        float4 w4 = wssr[f];
        v[j*4+0] = __fsub_rn(__fadd_rn(rss, w4.x), 2.0f * d4.x);
        v[j*4+1] = __fsub_rn(__fadd_rn(rss, w4.y), 2.0f * d4.y);
        v[j*4+2] = __fsub_rn(__fadd_rn(rss, w4.z), 2.0f * d4.z);
        v[j*4+3] = __fsub_rn(__fadd_rn(rss, w4.w), 2.0f * d4.w);
    }
    float best = v[0]; int bidx = lane * 4;
    #pragma unroll
    for (int j = 0; j < 4; j++)
        #pragma unroll
        for (int c = 0; c < 4; c++) {
            int k = (lane + j * 32) * 4 + c;
            float vv = v[j * 4 + c];
            if (vv < best || (vv == best && k < bidx)) { best = vv; bidx = k; }
        }
    #pragma unroll
    for (int o = 16; o; o >>= 1) {
        float ob = __shfl_down_sync(0xffffffffu, best, o);
        int   oi = __shfl_down_sync(0xffffffffu, bidx, o);
        if (ob < best || (ob == best && oi < bidx)) { best = ob; bidx = oi; }
    }
    best = __shfl_sync(0xffffffffu, best, 0);
    bidx = __shfl_sync(0xffffffffu, bidx, 0);

    float esum = 0.f;
    float sh[16];
    #pragma unroll
    for (int j = 0; j < 16; j++) {
        sh[j] = __fsub_rn(best, v[j]);
        esum += expf(sh[j]);
    }
    #pragma unroll
    for (int o = 16; o; o >>= 1) esum += __shfl_down_sync(0xffffffffu, esum, o);
    esum = __shfl_sync(0xffffffffu, esum, 0);
    float L = logf(esum);
    float psum = 0.f;
    #pragma unroll
    for (int j = 0; j < 16; j++) psum += __fsub_rn(sh[j], L);
    #pragma unroll
    for (int o = 16; o; o >>= 1) psum += __shfl_down_sync(0xffffffffu, psum, o);

    // fused one-hot probs row for (n, l)
    if (o_p >= 0) {
        float* pr = out + o_p + ((size_t)n * LLV + l) * KCB;
        #pragma unroll
        for (int j = 0; j < 4; j++) {
            int f = lane + j * 32;
            float4 v4 = make_float4(0.f, 0.f, 0.f, 0.f);
            if ((bidx >> 2) == f) ((float*)&v4)[bidx & 3] = 1.0f;
            *(float4*)(pr + 4 * f) = v4;
        }
    }

    if (lane == 0) {
        float mean = psum * (1.0f / 512.0f);
        float kl = __fsub_rn(-6.238324625039508f, mean);     // -log(512) - mean
        float klw = __fmul_rn(kl, 0.1f);
        g_kl[n] = (l == 0) ? klw : __fadd_rn(g_kl[n], klw);  // fl(0+x)==x bitwise
        g_idx[n * LLV + l] = bidx;
        g_pidx[n] = bidx;
        if (o_i >= 0) out[o_i + (size_t)n * LLV + l] = (float)bidx;
    }
}

// ---------------- g update: per-column sequential fp32 chain (bit-identical) -------
#define GCHAIN_SMEM ((KCB + NTOK) * 4)
__global__ __launch_bounds__(256) void k_gchain(const float* __restrict__ W, int l) {
    extern __shared__ __align__(16) float dyn[];
    float* scol = dyn;            // [KCB]
    float* vbuf = dyn + KCB;      // [NTOK]
    int d = blockIdx.x;
    int tid = threadIdx.x;
    const float* Wl = W + (size_t)l * KCB * DDIM + d;

    scol[tid]       = Wl[(size_t)tid * DDIM];
    scol[tid + 256] = Wl[(size_t)(tid + 256) * DDIM];
    __syncthreads();

    #pragma unroll
    for (int j = 0; j < NTOK / 256; j++) {
        int n = tid + j * 256;
        vbuf[n] = scol[g_pidx[n]];
    }
    __syncthreads();

    if (tid == 0) {
        float part = 0.f;
        const float4* b4 = (const float4*)vbuf;
        #pragma unroll 16
        for (int j = 0; j < NTOK / 4; j++) {
            float4 q = b4[j];
            part = __fadd_rn(part, q.x);
            part = __fadd_rn(part, q.y);
            part = __fadd_rn(part, q.z);
            part = __fadd_rn(part, q.w);
        }
        g_g[d] = __fadd_rn(g_g[d], part);
    }
}

// ---------------- q_out (transposed write) + per-token loss ----------------
__global__ void k_final_q(const float* __restrict__ W, float* __restrict__ out,
                          long long o_q) {
    __shared__ int   sidx[32][8];
    __shared__ float sq[32][257];
    int tid = threadIdx.x;
    int tbase = blockIdx.x * 32;
    sidx[tid >> 3][tid & 7] = g_idx[(tbase + (tid >> 3)) * LLV + (tid & 7)];
    __syncthreads();

    int d = tid;
    for (int t = 0; t < 32; t++) {
        float acc = 0.f;
        #pragma unroll
        for (int l = 0; l < LLV; l++)
            acc = __fadd_rn(acc, W[(size_t)(l * KCB + sidx[t][l]) * DDIM + d]);
        sq[t][d] = acc;
    }
    if (tid < 32) {
        int n = tbase + tid;
        float nl = 0.f;
        float un = g_normW[sidx[tid][0]];
        #pragma unroll
        for (int l = 0; l < 7; l++) {
            float lo = g_normW[(l + 1) * KCB + sidx[tid][l + 1]];
            float r  = fmaxf(__fmul_rn(__fdiv_rn(lo, un), 4.0f), 1.0f) - 1.0f;
            nl = __fadd_rn(nl, __fmul_rn(r, r));
            un = lo;
        }
        float nlm = __fdiv_rn(nl, 7.0f);
        g_ltok[n] = __fadd_rn(g_kl[n], __fmul_rn(nlm, 0.1f));
    }
    __syncthreads();
    if (o_q >= 0) {
        int b   = tbase >> 10;
        int hw0 = tbase & 1023;
        float* dst = out + o_q + (size_t)b * (DDIM * 1024);
        for (int it = 0; it < 32; it++) {
            int e = it * 256 + tid;
            int t = e & 31;
            int dd = e >> 5;
            dst[(size_t)dd * 1024 + hw0 + t] = sq[t][dd];
        }
    }
}

// ---------------- per-batch loss mean (parallel tree; loss output is tolerant) -----
__global__ void k_final_loss(float* __restrict__ out, long long o_l) {
    __shared__ float sh[8];
    int b = blockIdx.x, tid = threadIdx.x;
    int warp = tid >> 5, lane = tid & 31;
    float s = 0.f;
    #pragma unroll
    for (int i = 0; i < 4; i++)
        s = __fadd_rn(s, g_ltok[b * 1024 + tid + i * 256]);
    #pragma unroll
    for (int o = 16; o; o >>= 1) s += __shfl_down_sync(0xffffffffu, s, o);
    if (lane == 0) sh[warp] = s;
    __syncthreads();
    if (tid == 0 && o_l >= 0) {
        float t = 0.f;
        #pragma unroll
        for (int wdx = 0; wdx < 8; wdx++) t = __fadd_rn(t, sh[wdx]);
        out[o_l + b] = t * (1.0f / 1024.0f);
    }
}

// ---------------- launch ----------------
extern "C" void kernel_launch(void* const* d_in, const int* in_sizes, int n_in,
                              void* d_out, int out_size) {
    const float* z = nullptr;
    const float* w = nullptr;
    for (int i = 0; i < n_in; i++) {
        if (in_sizes[i] == NTOK * DDIM)            z = (const float*)d_in[i];
        else if (in_sizes[i] == LLV * KCB * DDIM)  w = (const float*)d_in[i];
    }
    float* out = (float*)d_out;

    const long long SZ_Q = (long long)BATCH * DDIM * 1024;   // 4194304
    const long long SZ_I = (long long)NTOK * LLV;            // 131072
    const long long SZ_L = BATCH;                            // 16
    const long long SZ_P = (long long)NTOK * LLV * KCB;      // 67108864
    long long o_q = 0, o_i = -1, o_l = -1, o_p = -1;
    long long total = SZ_Q + SZ_I + SZ_L + SZ_P;
    if ((long long)out_size >= total) { o_i = SZ_Q; o_l = o_i + SZ_I; o_p = o_l + SZ_L; }
    else cudaMemsetAsync(d_out, 0, (size_t)out_size * sizeof(float), 0);  // fallback only

    cudaFuncSetAttribute(k_gchain, cudaFuncAttributeMaxDynamicSharedMemorySize,
                         GCHAIN_SMEM);

    k_init<<<16, 256>>>(w);
    for (int l = 0; l < LLV; l++) {
        k_gemm<<<dim3(4, 128), 256>>>(z, w + (size_t)l * KCB * DDIM);
        k_reduce<<<2048, 256>>>(z, l, out, o_i, o_p);
        if (l < LLV - 1) k_gchain<<<DDIM, 256, GCHAIN_SMEM>>>(w, l);
    }
    k_final_q<<<512, 256>>>(w, out, o_q);
    k_final_loss<<<BATCH, 256>>>(out, o_l);
}

// round 15
// speedup vs baseline: 1.0496x; 1.0021x over previous
#include <cuda_runtime.h>
#include <math.h>

#define NTOK 16384
#define DDIM 256
#define KCB  512
#define LLV  8
#define BATCH 16

// ---------------- device scratch (static, no allocations) ----------------
__device__ float g_S[NTOK * KCB];      // raw dot[n,k] for current level (32 MB)
__device__ float g_g[DDIM];            // global_sum, fp32, reference-exact chain
__device__ float g_wss[LLV * KCB];     // ||W_k||^2
__device__ float g_normW[LLV * KCB];   // ||W_k||
__device__ float g_kl[NTOK];           // kl accumulator
__device__ int   g_idx[NTOK * LLV];    // picks (strided by level)
__device__ int   g_pidx[NTOK];         // packed picks for current level
__device__ float g_ltok[NTOK];         // per-token loss

typedef unsigned long long ull;
struct __align__(16) u64x2 { ull a, b; };

__device__ __forceinline__ ull pk2(float lo, float hi) {
    ull r;
    asm("mov.b64 %0, {%1, %2};" : "=l"(r) : "f"(lo), "f"(hi));
    return r;
}
__device__ __forceinline__ void upk2(ull v, float& lo, float& hi) {
    asm("mov.b64 {%0, %1}, %2;" : "=f"(lo), "=f"(hi) : "l"(v));
}
__device__ __forceinline__ ull ffma2(ull a, ull b, ull c) {
    ull d;
    asm("fma.rn.f32x2 %0, %1, %2, %3;" : "=l"(d) : "l"(a), "l"(b), "l"(c));
    return d;
}

// ---------------- init: wss, norms, zero g ----------------
__global__ void k_init(const float* __restrict__ W) {
    int gid = blockIdx.x * blockDim.x + threadIdx.x;   // 16*256 = 4096
    if (gid < LLV * KCB) {
        const float4* row = (const float4*)(W + (size_t)gid * DDIM);
        float acc = 0.f;
        #pragma unroll 8
        for (int j = 0; j < DDIM / 4; j++) {
            float4 w4 = row[j];
            acc = __fadd_rn(acc, __fmul_rn(w4.x, w4.x));
            acc = __fadd_rn(acc, __fmul_rn(w4.y, w4.y));
            acc = __fadd_rn(acc, __fmul_rn(w4.z, w4.z));
            acc = __fadd_rn(acc, __fmul_rn(w4.w, w4.w));
        }
        g_wss[gid]   = acc;
        g_normW[gid] = sqrtf(acc);
    }
    if (gid < DDIM) g_g[gid] = 0.f;
}

// ---------------- GEMM (bit-frozen, round-10 verbatim): 128x128 tile, BK=16 -------
__global__ __launch_bounds__(256, 2) void k_gemm(const float* __restrict__ Z,
                                                 const float* __restrict__ W) {
    __shared__ __align__(16) float As[2][16][132];
    __shared__ __align__(16) float Bs[2][16][132];
    __shared__ float sg[DDIM];
    int tid = threadIdx.x;
    int bx = blockIdx.x, by = blockIdx.y;   // bx 0..3, by 0..127
    int tx = tid & 15, ty = tid >> 4;
    int ty4 = ty * 4, tx4 = tx * 4;
    int lrow = tid >> 2;                    // 0..63
    int lc4  = (tid & 3) * 4;               // 0,4,8,12
    const int RO = 64 * DDIM;               // +64 rows
    const float* Ap = Z + (size_t)(by * 128 + lrow) * DDIM + lc4;
    const float* Bp = W + (size_t)(bx * 128 + lrow) * DDIM + lc4;

    sg[tid] = g_g[tid];

    ull acc2[4][8];   // row-pairs x 8 cols
    #pragma unroll
    for (int p = 0; p < 4; p++)
        #pragma unroll
        for (int j = 0; j < 8; j++) acc2[p][j] = 0ull;

    float4 a0 = *(const float4*)Ap;
    float4 a1 = *(const float4*)(Ap + RO);
    float4 b0 = *(const float4*)Bp;
    float4 b1 = *(const float4*)(Bp + RO);
    __syncthreads();                          // sg visible

    {
        As[0][lc4 + 0][lrow] = __fsub_rn(a0.x, sg[lc4 + 0]);
        As[0][lc4 + 1][lrow] = __fsub_rn(a0.y, sg[lc4 + 1]);
        As[0][lc4 + 2][lrow] = __fsub_rn(a0.z, sg[lc4 + 2]);
        As[0][lc4 + 3][lrow] = __fsub_rn(a0.w, sg[lc4 + 3]);
        As[0][lc4 + 0][64 + lrow] = __fsub_rn(a1.x, sg[lc4 + 0]);
        As[0][lc4 + 1][64 + lrow] = __fsub_rn(a1.y, sg[lc4 + 1]);
        As[0][lc4 + 2][64 + lrow] = __fsub_rn(a1.z, sg[lc4 + 2]);
        As[0][lc4 + 3][64 + lrow] = __fsub_rn(a1.w, sg[lc4 + 3]);
        Bs[0][lc4 + 0][lrow] = b0.x; Bs[0][lc4 + 1][lrow] = b0.y;
        Bs[0][lc4 + 2][lrow] = b0.z; Bs[0][lc4 + 3][lrow] = b0.w;
        Bs[0][lc4 + 0][64 + lrow] = b1.x; Bs[0][lc4 + 1][64 + lrow] = b1.y;
        Bs[0][lc4 + 2][64 + lrow] = b1.z; Bs[0][lc4 + 3][64 + lrow] = b1.w;
    }
    a0 = *(const float4*)(Ap + 16);          // prefetch tile 1
    a1 = *(const float4*)(Ap + 16 + RO);
    b0 = *(const float4*)(Bp + 16);
    b1 = *(const float4*)(Bp + 16 + RO);
    __syncthreads();

    for (int t = 0; t < 16; t++) {
        int buf = t & 1;
        if (t + 1 < 16) {
            int nb = (t + 1) & 1;
            int k1 = (t + 1) * 16;
            As[nb][lc4 + 0][lrow] = __fsub_rn(a0.x, sg[k1 + lc4 + 0]);
            As[nb][lc4 + 1][lrow] = __fsub_rn(a0.y, sg[k1 + lc4 + 1]);
            As[nb][lc4 + 2][lrow] = __fsub_rn(a0.z, sg[k1 + lc4 + 2]);
            As[nb][lc4 + 3][lrow] = __fsub_rn(a0.w, sg[k1 + lc4 + 3]);
            As[nb][lc4 + 0][64 + lrow] = __fsub_rn(a1.x, sg[k1 + lc4 + 0]);
            As[nb][lc4 + 1][64 + lrow] = __fsub_rn(a1.y, sg[k1 + lc4 + 1]);
            As[nb][lc4 + 2][64 + lrow] = __fsub_rn(a1.z, sg[k1 + lc4 + 2]);
            As[nb][lc4 + 3][64 + lrow] = __fsub_rn(a1.w, sg[k1 + lc4 + 3]);
            Bs[nb][lc4 + 0][lrow] = b0.x; Bs[nb][lc4 + 1][lrow] = b0.y;
            Bs[nb][lc4 + 2][lrow] = b0.z; Bs[nb][lc4 + 3][lrow] = b0.w;
            Bs[nb][lc4 + 0][64 + lrow] = b1.x; Bs[nb][lc4 + 1][64 + lrow] = b1.y;
            Bs[nb][lc4 + 2][64 + lrow] = b1.z; Bs[nb][lc4 + 3][64 + lrow] = b1.w;
            if (t + 2 < 16) {
                int k2 = (t + 2) * 16;
                a0 = *(const float4*)(Ap + k2);
                a1 = *(const float4*)(Ap + k2 + RO);
                b0 = *(const float4*)(Bp + k2);
                b1 = *(const float4*)(Bp + k2 + RO);
            }
        }
        #pragma unroll
        for (int kk = 0; kk < 16; kk++) {    // ascending d: in-order FMA chain
            u64x2 aL = *(const u64x2*)&As[buf][kk][ty4];
            u64x2 aH = *(const u64x2*)&As[buf][kk][64 + ty4];
            float4 bl = *(const float4*)&Bs[buf][kk][tx4];
            float4 bh = *(const float4*)&Bs[buf][kk][64 + tx4];
            ull bb[8];
            bb[0] = pk2(bl.x, bl.x); bb[1] = pk2(bl.y, bl.y);
            bb[2] = pk2(bl.z, bl.z); bb[3] = pk2(bl.w, bl.w);
            bb[4] = pk2(bh.x, bh.x); bb[5] = pk2(bh.y, bh.y);
            bb[6] = pk2(bh.z, bh.z); bb[7] = pk2(bh.w, bh.w);
            #pragma unroll
            for (int j = 0; j < 8; j++) {
                acc2[0][j] = ffma2(aL.a, bb[j], acc2[0][j]);
                acc2[1][j] = ffma2(aL.b, bb[j], acc2[1][j]);
                acc2[2][j] = ffma2(aH.a, bb[j], acc2[2][j]);
                acc2[3][j] = ffma2(aH.b, bb[j], acc2[3][j]);
            }
        }
        __syncthreads();
    }

    #pragma unroll
    for (int p = 0; p < 4; p++) {
        int rbase = (p < 2) ? (ty4 + p * 2) : (64 + ty4 + (p - 2) * 2);
        float lo[8], hi[8];
        #pragma unroll
        for (int j = 0; j < 8; j++) upk2(acc2[p][j], lo[j], hi[j]);
        #pragma unroll
        for (int h = 0; h < 2; h++) {
            int r = by * 128 + rbase + h;
            const float* src = h ? hi : lo;
            float* dst = g_S + (size_t)r * KCB + bx * 128;
            float4 v0, v1;
            v0.x = src[0]; v0.y = src[1]; v0.z = src[2]; v0.w = src[3];
            v1.x = src[4]; v1.y = src[5]; v1.z = src[6]; v1.w = src[7];
            *(float4*)(dst + tx4)      = v0;
            *(float4*)(dst + 64 + tx4) = v1;
        }
    }
}

// ---------------- per-token: rss fused + m_k + argmin + KL (bit-frozen) + fused
// one-hot probs row + float index writes (round-10 verbatim) ----------------
__global__ void k_reduce(const float* __restrict__ Z, int l, float* __restrict__ out,
                         long long o_i, long long o_p) {
    int tid = threadIdx.x;
    int warp = tid >> 5, lane = tid & 31;
    int n = blockIdx.x * 8 + warp;

    const float4* zr = (const float4*)(Z + (size_t)n * DDIM);
    const float4* gr = (const float4*)g_g;
    float rss = 0.f;
    #pragma unroll
    for (int j = 0; j < 2; j++) {
        int f = lane + j * 32;
        float4 z4 = zr[f];
        float4 g4 = gr[f];
        float r;
        r = __fsub_rn(z4.x, g4.x); rss = __fadd_rn(rss, __fmul_rn(r, r));
        r = __fsub_rn(z4.y, g4.y); rss = __fadd_rn(rss, __fmul_rn(r, r));
        r = __fsub_rn(z4.z, g4.z); rss = __fadd_rn(rss, __fmul_rn(r, r));
        r = __fsub_rn(z4.w, g4.w); rss = __fadd_rn(rss, __fmul_rn(r, r));
    }
    #pragma unroll
    for (int o = 16; o; o >>= 1) rss += __shfl_down_sync(0xffffffffu, rss, o);
    rss = __shfl_sync(0xffffffffu, rss, 0);

    const float4* dotr = (const float4*)(g_S + (size_t)n * KCB);
    const float4* wssr = (const float4*)(g_wss + l * KCB);

    float v[16];
    #pragma unroll
    for (int j = 0; j < 4; j++) {
        int f = lane + j * 32;
        float4 d4 = dotr[f];
        float4 w4 = wssr[f];
        v[j*4+0] = __fsub_rn(__fadd_rn(rss, w4.x), 2.0f * d4.x);
        v[j*4+1] = __fsub_rn(__fadd_rn(rss, w4.y), 2.0f * d4.y);
        v[j*4+2] = __fsub_rn(__fadd_rn(rss, w4.z), 2.0f * d4.z);
        v[j*4+3] = __fsub_rn(__fadd_rn(rss, w4.w), 2.0f * d4.w);
    }
    float best = v[0]; int bidx = lane * 4;
    #pragma unroll
    for (int j = 0; j < 4; j++)
        #pragma unroll
        for (int c = 0; c < 4; c++) {
            int k = (lane + j * 32) * 4 + c;
            float vv = v[j * 4 + c];
            if (vv < best || (vv == best && k < bidx)) { best = vv; bidx = k; }
        }
    #pragma unroll
    for (int o = 16; o; o >>= 1) {
        float ob = __shfl_down_sync(0xffffffffu, best, o);
        int   oi = __shfl_down_sync(0xffffffffu, bidx, o);
        if (ob < best || (ob == best && oi < bidx)) { best = ob; bidx = oi; }
    }
    best = __shfl_sync(0xffffffffu, best, 0);
    bidx = __shfl_sync(0xffffffffu, bidx, 0);

    float esum = 0.f;
    float sh[16];
    #pragma unroll
    for (int j = 0; j < 16; j++) {
        sh[j] = __fsub_rn(best, v[j]);
        esum += expf(sh[j]);
    }
    #pragma unroll
    for (int o = 16; o; o >>= 1) esum += __shfl_down_sync(0xffffffffu, esum, o);
    esum = __shfl_sync(0xffffffffu, esum, 0);
    float L = logf(esum);
    float psum = 0.f;
    #pragma unroll
    for (int j = 0; j < 16; j++) psum += __fsub_rn(sh[j], L);
    #pragma unroll
    for (int o = 16; o; o >>= 1) psum += __shfl_down_sync(0xffffffffu, psum, o);

    // fused one-hot probs row for (n, l)
    if (o_p >= 0) {
        float* pr = out + o_p + ((size_t)n * LLV + l) * KCB;
        #pragma unroll
        for (int j = 0; j < 4; j++) {
            int f = lane + j * 32;
            float4 v4 = make_float4(0.f, 0.f, 0.f, 0.f);
            if ((bidx >> 2) == f) ((float*)&v4)[bidx & 3] = 1.0f;
            *(float4*)(pr + 4 * f) = v4;
        }
    }

    if (lane == 0) {
        float mean = psum * (1.0f / 512.0f);
        float kl = __fsub_rn(-6.238324625039508f, mean);     // -log(512) - mean
        float klw = __fmul_rn(kl, 0.1f);
        g_kl[n] = (l == 0) ? klw : __fadd_rn(g_kl[n], klw);  // fl(0+x)==x bitwise
        g_idx[n * LLV + l] = bidx;
        g_pidx[n] = bidx;
        if (o_i >= 0) out[o_i + (size_t)n * LLV + l] = (float)bidx;
    }
}

// ---------------- g update: per-column sequential fp32 chain (bit-identical) -------
#define GCHAIN_SMEM ((KCB + NTOK) * 4)
__global__ __launch_bounds__(256) void k_gchain(const float* __restrict__ W, int l) {
    extern __shared__ __align__(16) float dyn[];
    float* scol = dyn;            // [KCB]
    float* vbuf = dyn + KCB;      // [NTOK]
    int d = blockIdx.x;
    int tid = threadIdx.x;
    const float* Wl = W + (size_t)l * KCB * DDIM + d;

    scol[tid]       = Wl[(size_t)tid * DDIM];
    scol[tid + 256] = Wl[(size_t)(tid + 256) * DDIM];
    __syncthreads();

    #pragma unroll
    for (int j = 0; j < NTOK / 256; j++) {
        int n = tid + j * 256;
        vbuf[n] = scol[g_pidx[n]];
    }
    __syncthreads();

    if (tid == 0) {
        float part = 0.f;
        const float4* b4 = (const float4*)vbuf;
        #pragma unroll 16
        for (int j = 0; j < NTOK / 4; j++) {
            float4 q = b4[j];
            part = __fadd_rn(part, q.x);
            part = __fadd_rn(part, q.y);
            part = __fadd_rn(part, q.z);
            part = __fadd_rn(part, q.w);
        }
        g_g[d] = __fadd_rn(g_g[d], part);
    }
}

// ---------------- q_out (transposed write) + per-token loss, 16 tokens/block ------
__global__ void k_final_q(const float* __restrict__ W, float* __restrict__ out,
                          long long o_q) {
    __shared__ int   sidx[16][8];
    __shared__ float sq[16][257];
    int tid = threadIdx.x;
    int tbase = blockIdx.x * 16;
    if (tid < 128) sidx[tid >> 3][tid & 7] = g_idx[(tbase + (tid >> 3)) * LLV + (tid & 7)];
    __syncthreads();

    int d = tid;
    for (int t = 0; t < 16; t++) {
        float acc = 0.f;
        #pragma unroll
        for (int l = 0; l < LLV; l++)
            acc = __fadd_rn(acc, W[(size_t)(l * KCB + sidx[t][l]) * DDIM + d]);
        sq[t][d] = acc;
    }
    if (tid < 16) {
        int n = tbase + tid;
        float nl = 0.f;
        float un = g_normW[sidx[tid][0]];
        #pragma unroll
        for (int l = 0; l < 7; l++) {
            float lo = g_normW[(l + 1) * KCB + sidx[tid][l + 1]];
            float r  = fmaxf(__fmul_rn(__fdiv_rn(lo, un), 4.0f), 1.0f) - 1.0f;
            nl = __fadd_rn(nl, __fmul_rn(r, r));
            un = lo;
        }
        float nlm = __fdiv_rn(nl, 7.0f);
        g_ltok[n] = __fadd_rn(g_kl[n], __fmul_rn(nlm, 0.1f));
    }
    __syncthreads();
    if (o_q >= 0) {
        int b   = tbase >> 10;
        int hw0 = tbase & 1023;
        float* dst = out + o_q + (size_t)b * (DDIM * 1024);
        for (int it = 0; it < 16; it++) {
            int e = it * 256 + tid;
            int t = e & 15;
            int dd = e >> 4;
            dst[(size_t)dd * 1024 + hw0 + t] = sq[t][dd];
        }
    }
}

// ---------------- per-batch loss mean (parallel tree; loss output is tolerant) -----
__global__ void k_final_loss(float* __restrict__ out, long long o_l) {
    __shared__ float sh[8];
    int b = blockIdx.x, tid = threadIdx.x;
    int warp = tid >> 5, lane = tid & 31;
    float s = 0.f;
    #pragma unroll
    for (int i = 0; i < 4; i++)
        s = __fadd_rn(s, g_ltok[b * 1024 + tid + i * 256]);
    #pragma unroll
    for (int o = 16; o; o >>= 1) s += __shfl_down_sync(0xffffffffu, s, o);
    if (lane == 0) sh[warp] = s;
    __syncthreads();
    if (tid == 0 && o_l >= 0) {
        float t = 0.f;
        #pragma unroll
        for (int wdx = 0; wdx < 8; wdx++) t = __fadd_rn(t, sh[wdx]);
        out[o_l + b] = t * (1.0f / 1024.0f);
    }
}

// ---------------- launch ----------------
extern "C" void kernel_launch(void* const* d_in, const int* in_sizes, int n_in,
                              void* d_out, int out_size) {
    const float* z = nullptr;
    const float* w = nullptr;
    for (int i = 0; i < n_in; i++) {
        if (in_sizes[i] == NTOK * DDIM)            z = (const float*)d_in[i];
        else if (in_sizes[i] == LLV * KCB * DDIM)  w = (const float*)d_in[i];
    }
    float* out = (float*)d_out;

    const long long SZ_Q = (long long)BATCH * DDIM * 1024;   // 4194304
    const long long SZ_I = (long long)NTOK * LLV;            // 131072
    const long long SZ_L = BATCH;                            // 16
    const long long SZ_P = (long long)NTOK * LLV * KCB;      // 67108864
    long long o_q = 0, o_i = -1, o_l = -1, o_p = -1;
    long long total = SZ_Q + SZ_I + SZ_L + SZ_P;
    if ((long long)out_size >= total) { o_i = SZ_Q; o_l = o_i + SZ_I; o_p = o_l + SZ_L; }
    else cudaMemsetAsync(d_out, 0, (size_t)out_size * sizeof(float), 0);  // fallback only

    cudaFuncSetAttribute(k_gchain, cudaFuncAttributeMaxDynamicSharedMemorySize,
                         GCHAIN_SMEM);

    k_init<<<16, 256>>>(w);
    for (int l = 0; l < LLV; l++) {
        k_gemm<<<dim3(4, 128), 256>>>(z, w + (size_t)l * KCB * DDIM);
        k_reduce<<<2048, 256>>>(z, l, out, o_i, o_p);
        if (l < LLV - 1) k_gchain<<<DDIM, 256, GCHAIN_SMEM>>>(w, l);
    }
    k_final_q<<<1024, 256>>>(w, out, o_q);
    k_final_loss<<<BATCH, 256>>>(out, o_l);
}

// round 16
// speedup vs baseline: 1.0605x; 1.0104x over previous
#include <cuda_runtime.h>
#include <math.h>

#define NTOK 16384
#define DDIM 256
#define KCB  512
#define LLV  8
#define BATCH 16

// ---------------- device scratch (static, no allocations) ----------------
__device__ float g_S[NTOK * KCB];      // raw dot[n,k] for current level (32 MB)
__device__ float g_g[DDIM];            // global_sum, fp32, reference-exact chain
__device__ float g_wss[LLV * KCB];     // ||W_k||^2
__device__ float g_normW[LLV * KCB];   // ||W_k||
__device__ float g_kl[NTOK];           // kl accumulator
__device__ int   g_idx[NTOK * LLV];    // picks (strided by level)
__device__ int   g_pidx[NTOK];         // packed picks for current level
__device__ float g_ltok[NTOK];         // per-token loss

typedef unsigned long long ull;
struct __align__(16) u64x2 { ull a, b; };

__device__ __forceinline__ ull pk2(float lo, float hi) {
    ull r;
    asm("mov.b64 %0, {%1, %2};" : "=l"(r) : "f"(lo), "f"(hi));
    return r;
}
__device__ __forceinline__ void upk2(ull v, float& lo, float& hi) {
    asm("mov.b64 {%0, %1}, %2;" : "=f"(lo), "=f"(hi) : "l"(v));
}
__device__ __forceinline__ ull ffma2(ull a, ull b, ull c) {
    ull d;
    asm("fma.rn.f32x2 %0, %1, %2, %3;" : "=l"(d) : "l"(a), "l"(b), "l"(c));
    return d;
}

// ---------------- init: wss, norms, zero g ----------------
__global__ void k_init(const float* __restrict__ W) {
    int gid = blockIdx.x * blockDim.x + threadIdx.x;   // 16*256 = 4096
    if (gid < LLV * KCB) {
        const float4* row = (const float4*)(W + (size_t)gid * DDIM);
        float acc = 0.f;
        #pragma unroll 8
        for (int j = 0; j < DDIM / 4; j++) {
            float4 w4 = row[j];
            acc = __fadd_rn(acc, __fmul_rn(w4.x, w4.x));
            acc = __fadd_rn(acc, __fmul_rn(w4.y, w4.y));
            acc = __fadd_rn(acc, __fmul_rn(w4.z, w4.z));
            acc = __fadd_rn(acc, __fmul_rn(w4.w, w4.w));
        }
        g_wss[gid]   = acc;
        g_normW[gid] = sqrtf(acc);
    }
    if (gid < DDIM) g_g[gid] = 0.f;
}

// ---------------- GEMM (bit-frozen chains; PDL: prefetch before griddep wait) -----
__global__ __launch_bounds__(256, 2) void k_gemm(const float* __restrict__ Z,
                                                 const float* __restrict__ W) {
    __shared__ __align__(16) float As[2][16][132];
    __shared__ __align__(16) float Bs[2][16][132];
    __shared__ float sg[DDIM];
    int tid = threadIdx.x;
    int bx = blockIdx.x, by = blockIdx.y;   // bx 0..3, by 0..127
    int tx = tid & 15, ty = tid >> 4;
    int ty4 = ty * 4, tx4 = tx * 4;
    int lrow = tid >> 2;                    // 0..63
    int lc4  = (tid & 3) * 4;               // 0,4,8,12
    const int RO = 64 * DDIM;               // +64 rows
    const float* Ap = Z + (size_t)(by * 128 + lrow) * DDIM + lc4;
    const float* Bp = W + (size_t)(bx * 128 + lrow) * DDIM + lc4;

    ull acc2[4][8];   // row-pairs x 8 cols
    #pragma unroll
    for (int p = 0; p < 4; p++)
        #pragma unroll
        for (int j = 0; j < 8; j++) acc2[p][j] = 0ull;

    // ---- pre-dependency region: Z/W tile-0 loads + Bs store (independent of g) ----
    float4 a0 = *(const float4*)Ap;
    float4 a1 = *(const float4*)(Ap + RO);
    float4 b0 = *(const float4*)Bp;
    float4 b1 = *(const float4*)(Bp + RO);
    Bs[0][lc4 + 0][lrow] = b0.x; Bs[0][lc4 + 1][lrow] = b0.y;
    Bs[0][lc4 + 2][lrow] = b0.z; Bs[0][lc4 + 3][lrow] = b0.w;
    Bs[0][lc4 + 0][64 + lrow] = b1.x; Bs[0][lc4 + 1][64 + lrow] = b1.y;
    Bs[0][lc4 + 2][64 + lrow] = b1.z; Bs[0][lc4 + 3][64 + lrow] = b1.w;

    // ---- wait for predecessor (gchain / init) to finish writing g_g ----
    asm volatile("griddepcontrol.wait;" ::: "memory");
    sg[tid] = g_g[tid];
    __syncthreads();                          // sg + Bs tile 0 visible

    {
        As[0][lc4 + 0][lrow] = __fsub_rn(a0.x, sg[lc4 + 0]);
        As[0][lc4 + 1][lrow] = __fsub_rn(a0.y, sg[lc4 + 1]);
        As[0][lc4 + 2][lrow] = __fsub_rn(a0.z, sg[lc4 + 2]);
        As[0][lc4 + 3][lrow] = __fsub_rn(a0.w, sg[lc4 + 3]);
        As[0][lc4 + 0][64 + lrow] = __fsub_rn(a1.x, sg[lc4 + 0]);
        As[0][lc4 + 1][64 + lrow] = __fsub_rn(a1.y, sg[lc4 + 1]);
        As[0][lc4 + 2][64 + lrow] = __fsub_rn(a1.z, sg[lc4 + 2]);
        As[0][lc4 + 3][64 + lrow] = __fsub_rn(a1.w, sg[lc4 + 3]);
    }
    a0 = *(const float4*)(Ap + 16);          // prefetch tile 1
    a1 = *(const float4*)(Ap + 16 + RO);
    b0 = *(const float4*)(Bp + 16);
    b1 = *(const float4*)(Bp + 16 + RO);
    __syncthreads();

    for (int t = 0; t < 16; t++) {
        int buf = t & 1;
        if (t + 1 < 16) {
            int nb = (t + 1) & 1;
            int k1 = (t + 1) * 16;
            As[nb][lc4 + 0][lrow] = __fsub_rn(a0.x, sg[k1 + lc4 + 0]);
            As[nb][lc4 + 1][lrow] = __fsub_rn(a0.y, sg[k1 + lc4 + 1]);
            As[nb][lc4 + 2][lrow] = __fsub_rn(a0.z, sg[k1 + lc4 + 2]);
            As[nb][lc4 + 3][lrow] = __fsub_rn(a0.w, sg[k1 + lc4 + 3]);
            As[nb][lc4 + 0][64 + lrow] = __fsub_rn(a1.x, sg[k1 + lc4 + 0]);
            As[nb][lc4 + 1][64 + lrow] = __fsub_rn(a1.y, sg[k1 + lc4 + 1]);
            As[nb][lc4 + 2][64 + lrow] = __fsub_rn(a1.z, sg[k1 + lc4 + 2]);
            As[nb][lc4 + 3][64 + lrow] = __fsub_rn(a1.w, sg[k1 + lc4 + 3]);
            Bs[nb][lc4 + 0][lrow] = b0.x; Bs[nb][lc4 + 1][lrow] = b0.y;
            Bs[nb][lc4 + 2][lrow] = b0.z; Bs[nb][lc4 + 3][lrow] = b0.w;
            Bs[nb][lc4 + 0][64 + lrow] = b1.x; Bs[nb][lc4 + 1][64 + lrow] = b1.y;
            Bs[nb][lc4 + 2][64 + lrow] = b1.z; Bs[nb][lc4 + 3][64 + lrow] = b1.w;
            if (t + 2 < 16) {
                int k2 = (t + 2) * 16;
                a0 = *(const float4*)(Ap + k2);
                a1 = *(const float4*)(Ap + k2 + RO);
                b0 = *(const float4*)(Bp + k2);
                b1 = *(const float4*)(Bp + k2 + RO);
            }
        }
        #pragma unroll
        for (int kk = 0; kk < 16; kk++) {    // ascending d: in-order FMA chain
            u64x2 aL = *(const u64x2*)&As[buf][kk][ty4];
            u64x2 aH = *(const u64x2*)&As[buf][kk][64 + ty4];
            float4 bl = *(const float4*)&Bs[buf][kk][tx4];
            float4 bh = *(const float4*)&Bs[buf][kk][64 + tx4];
            ull bb[8];
            bb[0] = pk2(bl.x, bl.x); bb[1] = pk2(bl.y, bl.y);
            bb[2] = pk2(bl.z, bl.z); bb[3] = pk2(bl.w, bl.w);
            bb[4] = pk2(bh.x, bh.x); bb[5] = pk2(bh.y, bh.y);
            bb[6] = pk2(bh.z, bh.z); bb[7] = pk2(bh.w, bh.w);
            #pragma unroll
            for (int j = 0; j < 8; j++) {
                acc2[0][j] = ffma2(aL.a, bb[j], acc2[0][j]);
                acc2[1][j] = ffma2(aL.b, bb[j], acc2[1][j]);
                acc2[2][j] = ffma2(aH.a, bb[j], acc2[2][j]);
                acc2[3][j] = ffma2(aH.b, bb[j], acc2[3][j]);
            }
        }
        __syncthreads();
    }

    #pragma unroll
    for (int p = 0; p < 4; p++) {
        int rbase = (p < 2) ? (ty4 + p * 2) : (64 + ty4 + (p - 2) * 2);
        float lo[8], hi[8];
        #pragma unroll
        for (int j = 0; j < 8; j++) upk2(acc2[p][j], lo[j], hi[j]);
        #pragma unroll
        for (int h = 0; h < 2; h++) {
            int r = by * 128 + rbase + h;
            const float* src = h ? hi : lo;
            float* dst = g_S + (size_t)r * KCB + bx * 128;
            float4 v0, v1;
            v0.x = src[0]; v0.y = src[1]; v0.z = src[2]; v0.w = src[3];
            v1.x = src[4]; v1.y = src[5]; v1.z = src[6]; v1.w = src[7];
            *(float4*)(dst + tx4)      = v0;
            *(float4*)(dst + 64 + tx4) = v1;
        }
    }
}

// ---------------- per-token: rss fused + m_k + argmin + KL (bit-frozen) + fused
// one-hot probs row + float index writes ----------------
__global__ void k_reduce(const float* __restrict__ Z, int l, float* __restrict__ out,
                         long long o_i, long long o_p) {
    int tid = threadIdx.x;
    int warp = tid >> 5, lane = tid & 31;
    int n = blockIdx.x * 8 + warp;

    const float4* zr = (const float4*)(Z + (size_t)n * DDIM);
    const float4* gr = (const float4*)g_g;
    float rss = 0.f;
    #pragma unroll
    for (int j = 0; j < 2; j++) {
        int f = lane + j * 32;
        float4 z4 = zr[f];
        float4 g4 = gr[f];
        float r;
        r = __fsub_rn(z4.x, g4.x); rss = __fadd_rn(rss, __fmul_rn(r, r));
        r = __fsub_rn(z4.y, g4.y); rss = __fadd_rn(rss, __fmul_rn(r, r));
        r = __fsub_rn(z4.z, g4.z); rss = __fadd_rn(rss, __fmul_rn(r, r));
        r = __fsub_rn(z4.w, g4.w); rss = __fadd_rn(rss, __fmul_rn(r, r));
    }
    #pragma unroll
    for (int o = 16; o; o >>= 1) rss += __shfl_down_sync(0xffffffffu, rss, o);
    rss = __shfl_sync(0xffffffffu, rss, 0);

    const float4* dotr = (const float4*)(g_S + (size_t)n * KCB);
    const float4* wssr = (const float4*)(g_wss + l * KCB);

    float v[16];
    #pragma unroll
    for (int j = 0; j < 4; j++) {
        int f = lane + j * 32;
        float4 d4 = dotr[f];
        float4 w4 = wssr[f];
        v[j*4+0] = __fsub_rn(__fadd_rn(rss, w4.x), 2.0f * d4.x);
        v[j*4+1] = __fsub_rn(__fadd_rn(rss, w4.y), 2.0f * d4.y);
        v[j*4+2] = __fsub_rn(__fadd_rn(rss, w4.z), 2.0f * d4.z);
        v[j*4+3] = __fsub_rn(__fadd_rn(rss, w4.w), 2.0f * d4.w);
    }
    float best = v[0]; int bidx = lane * 4;
    #pragma unroll
    for (int j = 0; j < 4; j++)
        #pragma unroll
        for (int c = 0; c < 4; c++) {
            int k = (lane + j * 32) * 4 + c;
            float vv = v[j * 4 + c];
            if (vv < best || (vv == best && k < bidx)) { best = vv; bidx = k; }
        }
    #pragma unroll
    for (int o = 16; o; o >>= 1) {
        float ob = __shfl_down_sync(0xffffffffu, best, o);
        int   oi = __shfl_down_sync(0xffffffffu, bidx, o);
        if (ob < best || (ob == best && oi < bidx)) { best = ob; bidx = oi; }
    }
    best = __shfl_sync(0xffffffffu, best, 0);
    bidx = __shfl_sync(0xffffffffu, bidx, 0);

    float esum = 0.f;
    float sh[16];
    #pragma unroll
    for (int j = 0; j < 16; j++) {
        sh[j] = __fsub_rn(best, v[j]);
        esum += expf(sh[j]);
    }
    #pragma unroll
    for (int o = 16; o; o >>= 1) esum += __shfl_down_sync(0xffffffffu, esum, o);
    esum = __shfl_sync(0xffffffffu, esum, 0);
    float L = logf(esum);
    float psum = 0.f;
    #pragma unroll
    for (int j = 0; j < 16; j++) psum += __fsub_rn(sh[j], L);
    #pragma unroll
    for (int o = 16; o; o >>= 1) psum += __shfl_down_sync(0xffffffffu, psum, o);

    // fused one-hot probs row for (n, l)
    if (o_p >= 0) {
        float* pr = out + o_p + ((size_t)n * LLV + l) * KCB;
        #pragma unroll
        for (int j = 0; j < 4; j++) {
            int f = lane + j * 32;
            float4 v4 = make_float4(0.f, 0.f, 0.f, 0.f);
            if ((bidx >> 2) == f) ((float*)&v4)[bidx & 3] = 1.0f;
            *(float4*)(pr + 4 * f) = v4;
        }
    }

    if (lane == 0) {
        float mean = psum * (1.0f / 512.0f);
        float kl = __fsub_rn(-6.238324625039508f, mean);     // -log(512) - mean
        float klw = __fmul_rn(kl, 0.1f);
        g_kl[n] = (l == 0) ? klw : __fadd_rn(g_kl[n], klw);  // fl(0+x)==x bitwise
        g_idx[n * LLV + l] = bidx;
        g_pidx[n] = bidx;
        if (o_i >= 0) out[o_i + (size_t)n * LLV + l] = (float)bidx;
    }
}

// ---------------- g update: per-column sequential fp32 chain (bit-identical) -------
#define GCHAIN_SMEM ((KCB + NTOK) * 4)
__global__ __launch_bounds__(256) void k_gchain(const float* __restrict__ W, int l) {
    extern __shared__ __align__(16) float dyn[];
    float* scol = dyn;            // [KCB]
    float* vbuf = dyn + KCB;      // [NTOK]
    int d = blockIdx.x;
    int tid = threadIdx.x;
    const float* Wl = W + (size_t)l * KCB * DDIM + d;

    scol[tid]       = Wl[(size_t)tid * DDIM];
    scol[tid + 256] = Wl[(size_t)(tid + 256) * DDIM];
    __syncthreads();

    #pragma unroll
    for (int j = 0; j < NTOK / 256; j++) {
        int n = tid + j * 256;
        vbuf[n] = scol[g_pidx[n]];
    }
    __syncthreads();

    if (tid == 0) {
        float part = 0.f;
        const float4* b4 = (const float4*)vbuf;
        #pragma unroll 16
        for (int j = 0; j < NTOK / 4; j++) {
            float4 q = b4[j];
            part = __fadd_rn(part, q.x);
            part = __fadd_rn(part, q.y);
            part = __fadd_rn(part, q.z);
            part = __fadd_rn(part, q.w);
        }
        g_g[d] = __fadd_rn(g_g[d], part);
    }
}

// ---------------- q_out (transposed write) + per-token loss, 16 tokens/block ------
__global__ void k_final_q(const float* __restrict__ W, float* __restrict__ out,
                          long long o_q) {
    __shared__ int   sidx[16][8];
    __shared__ float sq[16][257];
    int tid = threadIdx.x;
    int tbase = blockIdx.x * 16;
    if (tid < 128) sidx[tid >> 3][tid & 7] = g_idx[(tbase + (tid >> 3)) * LLV + (tid & 7)];
    __syncthreads();

    int d = tid;
    for (int t = 0; t < 16; t++) {
        float acc = 0.f;
        #pragma unroll
        for (int l = 0; l < LLV; l++)
            acc = __fadd_rn(acc, W[(size_t)(l * KCB + sidx[t][l]) * DDIM + d]);
        sq[t][d] = acc;
    }
    if (tid < 16) {
        int n = tbase + tid;
        float nl = 0.f;
        float un = g_normW[sidx[tid][0]];
        #pragma unroll
        for (int l = 0; l < 7; l++) {
            float lo = g_normW[(l + 1) * KCB + sidx[tid][l + 1]];
            float r  = fmaxf(__fmul_rn(__fdiv_rn(lo, un), 4.0f), 1.0f) - 1.0f;
            nl = __fadd_rn(nl, __fmul_rn(r, r));
            un = lo;
        }
        float nlm = __fdiv_rn(nl, 7.0f);
        g_ltok[n] = __fadd_rn(g_kl[n], __fmul_rn(nlm, 0.1f));
    }
    __syncthreads();
    if (o_q >= 0) {
        int b   = tbase >> 10;
        int hw0 = tbase & 1023;
        float* dst = out + o_q + (size_t)b * (DDIM * 1024);
        for (int it = 0; it < 16; it++) {
            int e = it * 256 + tid;
            int t = e & 15;
            int dd = e >> 4;
            dst[(size_t)dd * 1024 + hw0 + t] = sq[t][dd];
        }
    }
}

// ---------------- per-batch loss mean (parallel tree; loss output is tolerant) -----
__global__ void k_final_loss(float* __restrict__ out, long long o_l) {
    __shared__ float sh[8];
    int b = blockIdx.x, tid = threadIdx.x;
    int warp = tid >> 5, lane = tid & 31;
    float s = 0.f;
    #pragma unroll
    for (int i = 0; i < 4; i++)
        s = __fadd_rn(s, g_ltok[b * 1024 + tid + i * 256]);
    #pragma unroll
    for (int o = 16; o; o >>= 1) s += __shfl_down_sync(0xffffffffu, s, o);
    if (lane == 0) sh[warp] = s;
    __syncthreads();
    if (tid == 0 && o_l >= 0) {
        float t = 0.f;
        #pragma unroll
        for (int wdx = 0; wdx < 8; wdx++) t = __fadd_rn(t, sh[wdx]);
        out[o_l + b] = t * (1.0f / 1024.0f);
    }
}

// ---------------- launch (gemm uses PDL to overlap prelude with gchain tail) ------
extern "C" void kernel_launch(void* const* d_in, const int* in_sizes, int n_in,
                              void* d_out, int out_size) {
    const float* z = nullptr;
    const float* w = nullptr;
    for (int i = 0; i < n_in; i++) {
        if (in_sizes[i] == NTOK * DDIM)            z = (const float*)d_in[i];
        else if (in_sizes[i] == LLV * KCB * DDIM)  w = (const float*)d_in[i];
    }
    float* out = (float*)d_out;

    const long long SZ_Q = (long long)BATCH * DDIM * 1024;   // 4194304
    const long long SZ_I = (long long)NTOK * LLV;            // 131072
    const long long SZ_L = BATCH;                            // 16
    const long long SZ_P = (long long)NTOK * LLV * KCB;      // 67108864
    long long o_q = 0, o_i = -1, o_l = -1, o_p = -1;
    long long total = SZ_Q + SZ_I + SZ_L + SZ_P;
    if ((long long)out_size >= total) { o_i = SZ_Q; o_l = o_i + SZ_I; o_p = o_l + SZ_L; }
    else cudaMemsetAsync(d_out, 0, (size_t)out_size * sizeof(float), 0);  // fallback only

    cudaFuncSetAttribute(k_gchain, cudaFuncAttributeMaxDynamicSharedMemorySize,
                         GCHAIN_SMEM);

    k_init<<<16, 256>>>(w);
    for (int l = 0; l < LLV; l++) {
        // PDL launch: gemm's pre-wait region (Z/W tile-0 loads) overlaps the
        // predecessor (k_init / k_gchain) tail; griddepcontrol.wait in-kernel
        // orders the g_g read.
        cudaLaunchConfig_t cfg = {};
        cfg.gridDim  = dim3(4, 128, 1);
        cfg.blockDim = dim3(256, 1, 1);
        cfg.stream   = 0;
        cudaLaunchAttribute attr[1];
        attr[0].id = cudaLaunchAttributeProgrammaticStreamSerialization;
        attr[0].val.programmaticStreamSerializationAllowed = 1;
        cfg.attrs = attr;
        cfg.numAttrs = 1;
        const float* wl = w + (size_t)l * KCB * DDIM;
        if (cudaLaunchKernelEx(&cfg, k_gemm, z, wl) != cudaSuccess) {
            k_gemm<<<dim3(4, 128), 256>>>(z, wl);   // fallback: plain launch
        }
        k_reduce<<<2048, 256>>>(z, l, out, o_i, o_p);
        if (l < LLV - 1) k_gchain<<<DDIM, 256, GCHAIN_SMEM>>>(w, l);
    }
    k_final_q<<<1024, 256>>>(w, out, o_q);
    k_final_loss<<<BATCH, 256>>>(out, o_l);
}

// round 17
// speedup vs baseline: 1.0685x; 1.0076x over previous
#include <cuda_runtime.h>
#include <math.h>

#define NTOK 16384
#define DDIM 256
#define KCB  512
#define LLV  8
#define BATCH 16

// ---------------- device scratch (static, no allocations) ----------------
__device__ float g_S[NTOK * KCB];      // raw dot[n,k] for current level (32 MB)
__device__ float g_g[DDIM];            // global_sum, fp32, reference-exact chain
__device__ float g_wss[LLV * KCB];     // ||W_k||^2
__device__ float g_normW[LLV * KCB];   // ||W_k||
__device__ float g_kl[NTOK];           // kl accumulator
__device__ int   g_idx[NTOK * LLV];    // picks (strided by level)
__device__ int   g_pidx[NTOK];         // packed picks for current level
__device__ float g_ltok[NTOK];         // per-token loss

typedef unsigned long long ull;
struct __align__(16) u64x2 { ull a, b; };

__device__ __forceinline__ ull pk2(float lo, float hi) {
    ull r;
    asm("mov.b64 %0, {%1, %2};" : "=l"(r) : "f"(lo), "f"(hi));
    return r;
}
__device__ __forceinline__ void upk2(ull v, float& lo, float& hi) {
    asm("mov.b64 {%0, %1}, %2;" : "=f"(lo), "=f"(hi) : "l"(v));
}
__device__ __forceinline__ ull ffma2(ull a, ull b, ull c) {
    ull d;
    asm("fma.rn.f32x2 %0, %1, %2, %3;" : "=l"(d) : "l"(a), "l"(b), "l"(c));
    return d;
}
__device__ __forceinline__ void gdc_wait() {
    asm volatile("griddepcontrol.wait;" ::: "memory");
}

// ---------------- init: wss, norms, zero g ----------------
__global__ void k_init(const float* __restrict__ W) {
    int gid = blockIdx.x * blockDim.x + threadIdx.x;   // 16*256 = 4096
    if (gid < LLV * KCB) {
        const float4* row = (const float4*)(W + (size_t)gid * DDIM);
        float acc = 0.f;
        #pragma unroll 8
        for (int j = 0; j < DDIM / 4; j++) {
            float4 w4 = row[j];
            acc = __fadd_rn(acc, __fmul_rn(w4.x, w4.x));
            acc = __fadd_rn(acc, __fmul_rn(w4.y, w4.y));
            acc = __fadd_rn(acc, __fmul_rn(w4.z, w4.z));
            acc = __fadd_rn(acc, __fmul_rn(w4.w, w4.w));
        }
        g_wss[gid]   = acc;
        g_normW[gid] = sqrtf(acc);
    }
    if (gid < DDIM) g_g[gid] = 0.f;
}

// ---------------- GEMM (bit-frozen chains; PDL: prefetch before griddep wait) -----
__global__ __launch_bounds__(256, 2) void k_gemm(const float* __restrict__ Z,
                                                 const float* __restrict__ W) {
    __shared__ __align__(16) float As[2][16][132];
    __shared__ __align__(16) float Bs[2][16][132];
    __shared__ float sg[DDIM];
    int tid = threadIdx.x;
    int bx = blockIdx.x, by = blockIdx.y;   // bx 0..3, by 0..127
    int tx = tid & 15, ty = tid >> 4;
    int ty4 = ty * 4, tx4 = tx * 4;
    int lrow = tid >> 2;                    // 0..63
    int lc4  = (tid & 3) * 4;               // 0,4,8,12
    const int RO = 64 * DDIM;               // +64 rows
    const float* Ap = Z + (size_t)(by * 128 + lrow) * DDIM + lc4;
    const float* Bp = W + (size_t)(bx * 128 + lrow) * DDIM + lc4;

    ull acc2[4][8];   // row-pairs x 8 cols
    #pragma unroll
    for (int p = 0; p < 4; p++)
        #pragma unroll
        for (int j = 0; j < 8; j++) acc2[p][j] = 0ull;

    // ---- pre-dependency region: Z/W tile-0 loads + Bs store (independent of g) ----
    float4 a0 = *(const float4*)Ap;
    float4 a1 = *(const float4*)(Ap + RO);
    float4 b0 = *(const float4*)Bp;
    float4 b1 = *(const float4*)(Bp + RO);
    Bs[0][lc4 + 0][lrow] = b0.x; Bs[0][lc4 + 1][lrow] = b0.y;
    Bs[0][lc4 + 2][lrow] = b0.z; Bs[0][lc4 + 3][lrow] = b0.w;
    Bs[0][lc4 + 0][64 + lrow] = b1.x; Bs[0][lc4 + 1][64 + lrow] = b1.y;
    Bs[0][lc4 + 2][64 + lrow] = b1.z; Bs[0][lc4 + 3][64 + lrow] = b1.w;

    // ---- wait for predecessor (gchain / init) to finish writing g_g ----
    gdc_wait();
    sg[tid] = g_g[tid];
    __syncthreads();                          // sg + Bs tile 0 visible

    {
        As[0][lc4 + 0][lrow] = __fsub_rn(a0.x, sg[lc4 + 0]);
        As[0][lc4 + 1][lrow] = __fsub_rn(a0.y, sg[lc4 + 1]);
        As[0][lc4 + 2][lrow] = __fsub_rn(a0.z, sg[lc4 + 2]);
        As[0][lc4 + 3][lrow] = __fsub_rn(a0.w, sg[lc4 + 3]);
        As[0][lc4 + 0][64 + lrow] = __fsub_rn(a1.x, sg[lc4 + 0]);
        As[0][lc4 + 1][64 + lrow] = __fsub_rn(a1.y, sg[lc4 + 1]);
        As[0][lc4 + 2][64 + lrow] = __fsub_rn(a1.z, sg[lc4 + 2]);
        As[0][lc4 + 3][64 + lrow] = __fsub_rn(a1.w, sg[lc4 + 3]);
    }
    a0 = *(const float4*)(Ap + 16);          // prefetch tile 1
    a1 = *(const float4*)(Ap + 16 + RO);
    b0 = *(const float4*)(Bp + 16);
    b1 = *(const float4*)(Bp + 16 + RO);
    __syncthreads();

    for (int t = 0; t < 16; t++) {
        int buf = t & 1;
        if (t + 1 < 16) {
            int nb = (t + 1) & 1;
            int k1 = (t + 1) * 16;
            As[nb][lc4 + 0][lrow] = __fsub_rn(a0.x, sg[k1 + lc4 + 0]);
            As[nb][lc4 + 1][lrow] = __fsub_rn(a0.y, sg[k1 + lc4 + 1]);
            As[nb][lc4 + 2][lrow] = __fsub_rn(a0.z, sg[k1 + lc4 + 2]);
            As[nb][lc4 + 3][lrow] = __fsub_rn(a0.w, sg[k1 + lc4 + 3]);
            As[nb][lc4 + 0][64 + lrow] = __fsub_rn(a1.x, sg[k1 + lc4 + 0]);
            As[nb][lc4 + 1][64 + lrow] = __fsub_rn(a1.y, sg[k1 + lc4 + 1]);
            As[nb][lc4 + 2][64 + lrow] = __fsub_rn(a1.z, sg[k1 + lc4 + 2]);
            As[nb][lc4 + 3][64 + lrow] = __fsub_rn(a1.w, sg[k1 + lc4 + 3]);
            Bs[nb][lc4 + 0][lrow] = b0.x; Bs[nb][lc4 + 1][lrow] = b0.y;
            Bs[nb][lc4 + 2][lrow] = b0.z; Bs[nb][lc4 + 3][lrow] = b0.w;
            Bs[nb][lc4 + 0][64 + lrow] = b1.x; Bs[nb][lc4 + 1][64 + lrow] = b1.y;
            Bs[nb][lc4 + 2][64 + lrow] = b1.z; Bs[nb][lc4 + 3][64 + lrow] = b1.w;
            if (t + 2 < 16) {
                int k2 = (t + 2) * 16;
                a0 = *(const float4*)(Ap + k2);
                a1 = *(const float4*)(Ap + k2 + RO);
                b0 = *(const float4*)(Bp + k2);
                b1 = *(const float4*)(Bp + k2 + RO);
            }
        }
        #pragma unroll
        for (int kk = 0; kk < 16; kk++) {    // ascending d: in-order FMA chain
            u64x2 aL = *(const u64x2*)&As[buf][kk][ty4];
            u64x2 aH = *(const u64x2*)&As[buf][kk][64 + ty4];
            float4 bl = *(const float4*)&Bs[buf][kk][tx4];
            float4 bh = *(const float4*)&Bs[buf][kk][64 + tx4];
            ull bb[8];
            bb[0] = pk2(bl.x, bl.x); bb[1] = pk2(bl.y, bl.y);
            bb[2] = pk2(bl.z, bl.z); bb[3] = pk2(bl.w, bl.w);
            bb[4] = pk2(bh.x, bh.x); bb[5] = pk2(bh.y, bh.y);
            bb[6] = pk2(bh.z, bh.z); bb[7] = pk2(bh.w, bh.w);
            #pragma unroll
            for (int j = 0; j < 8; j++) {
                acc2[0][j] = ffma2(aL.a, bb[j], acc2[0][j]);
                acc2[1][j] = ffma2(aL.b, bb[j], acc2[1][j]);
                acc2[2][j] = ffma2(aH.a, bb[j], acc2[2][j]);
                acc2[3][j] = ffma2(aH.b, bb[j], acc2[3][j]);
            }
        }
        __syncthreads();
    }

    #pragma unroll
    for (int p = 0; p < 4; p++) {
        int rbase = (p < 2) ? (ty4 + p * 2) : (64 + ty4 + (p - 2) * 2);
        float lo[8], hi[8];
        #pragma unroll
        for (int j = 0; j < 8; j++) upk2(acc2[p][j], lo[j], hi[j]);
        #pragma unroll
        for (int h = 0; h < 2; h++) {
            int r = by * 128 + rbase + h;
            const float* src = h ? hi : lo;
            float* dst = g_S + (size_t)r * KCB + bx * 128;
            float4 v0, v1;
            v0.x = src[0]; v0.y = src[1]; v0.z = src[2]; v0.w = src[3];
            v1.x = src[4]; v1.y = src[5]; v1.z = src[6]; v1.w = src[7];
            *(float4*)(dst + tx4)      = v0;
            *(float4*)(dst + 64 + tx4) = v1;
        }
    }
}

// ---------------- per-token reduce (PDL: z-loads + rss before griddep wait) -------
// g_g is stable since gchain(l-1) finished before gemm(l) started.
__global__ void k_reduce(const float* __restrict__ Z, int l, float* __restrict__ out,
                         long long o_i, long long o_p) {
    int tid = threadIdx.x;
    int warp = tid >> 5, lane = tid & 31;
    int n = blockIdx.x * 8 + warp;

    // ---- pre-dependency region: rss (depends only on Z and stable g_g) ----
    const float4* zr = (const float4*)(Z + (size_t)n * DDIM);
    const float4* gr = (const float4*)g_g;
    float rss = 0.f;
    #pragma unroll
    for (int j = 0; j < 2; j++) {
        int f = lane + j * 32;
        float4 z4 = zr[f];
        float4 g4 = gr[f];
        float r;
        r = __fsub_rn(z4.x, g4.x); rss = __fadd_rn(rss, __fmul_rn(r, r));
        r = __fsub_rn(z4.y, g4.y); rss = __fadd_rn(rss, __fmul_rn(r, r));
        r = __fsub_rn(z4.z, g4.z); rss = __fadd_rn(rss, __fmul_rn(r, r));
        r = __fsub_rn(z4.w, g4.w); rss = __fadd_rn(rss, __fmul_rn(r, r));
    }
    #pragma unroll
    for (int o = 16; o; o >>= 1) rss += __shfl_down_sync(0xffffffffu, rss, o);
    rss = __shfl_sync(0xffffffffu, rss, 0);

    // ---- wait for gemm's g_S writes ----
    gdc_wait();

    const float4* dotr = (const float4*)(g_S + (size_t)n * KCB);
    const float4* wssr = (const float4*)(g_wss + l * KCB);

    float v[16];
    #pragma unroll
    for (int j = 0; j < 4; j++) {
        int f = lane + j * 32;
        float4 d4 = dotr[f];
        float4 w4 = wssr[f];
        v[j*4+0] = __fsub_rn(__fadd_rn(rss, w4.x), 2.0f * d4.x);
        v[j*4+1] = __fsub_rn(__fadd_rn(rss, w4.y), 2.0f * d4.y);
        v[j*4+2] = __fsub_rn(__fadd_rn(rss, w4.z), 2.0f * d4.z);
        v[j*4+3] = __fsub_rn(__fadd_rn(rss, w4.w), 2.0f * d4.w);
    }
    float best = v[0]; int bidx = lane * 4;
    #pragma unroll
    for (int j = 0; j < 4; j++)
        #pragma unroll
        for (int c = 0; c < 4; c++) {
            int k = (lane + j * 32) * 4 + c;
            float vv = v[j * 4 + c];
            if (vv < best || (vv == best && k < bidx)) { best = vv; bidx = k; }
        }
    #pragma unroll
    for (int o = 16; o; o >>= 1) {
        float ob = __shfl_down_sync(0xffffffffu, best, o);
        int   oi = __shfl_down_sync(0xffffffffu, bidx, o);
        if (ob < best || (ob == best && oi < bidx)) { best = ob; bidx = oi; }
    }
    best = __shfl_sync(0xffffffffu, best, 0);
    bidx = __shfl_sync(0xffffffffu, bidx, 0);

    float esum = 0.f;
    float sh[16];
    #pragma unroll
    for (int j = 0; j < 16; j++) {
        sh[j] = __fsub_rn(best, v[j]);
        esum += expf(sh[j]);
    }
    #pragma unroll
    for (int o = 16; o; o >>= 1) esum += __shfl_down_sync(0xffffffffu, esum, o);
    esum = __shfl_sync(0xffffffffu, esum, 0);
    float L = logf(esum);
    float psum = 0.f;
    #pragma unroll
    for (int j = 0; j < 16; j++) psum += __fsub_rn(sh[j], L);
    #pragma unroll
    for (int o = 16; o; o >>= 1) psum += __shfl_down_sync(0xffffffffu, psum, o);

    // fused one-hot probs row for (n, l)
    if (o_p >= 0) {
        float* pr = out + o_p + ((size_t)n * LLV + l) * KCB;
        #pragma unroll
        for (int j = 0; j < 4; j++) {
            int f = lane + j * 32;
            float4 v4 = make_float4(0.f, 0.f, 0.f, 0.f);
            if ((bidx >> 2) == f) ((float*)&v4)[bidx & 3] = 1.0f;
            *(float4*)(pr + 4 * f) = v4;
        }
    }

    if (lane == 0) {
        float mean = psum * (1.0f / 512.0f);
        float kl = __fsub_rn(-6.238324625039508f, mean);     // -log(512) - mean
        float klw = __fmul_rn(kl, 0.1f);
        g_kl[n] = (l == 0) ? klw : __fadd_rn(g_kl[n], klw);  // fl(0+x)==x bitwise
        g_idx[n * LLV + l] = bidx;
        g_pidx[n] = bidx;
        if (o_i >= 0) out[o_i + (size_t)n * LLV + l] = (float)bidx;
    }
}

// ---------------- g update (PDL: scol staging before griddep wait) ----------------
#define GCHAIN_SMEM ((KCB + NTOK) * 4)
__global__ __launch_bounds__(256) void k_gchain(const float* __restrict__ W, int l) {
    extern __shared__ __align__(16) float dyn[];
    float* scol = dyn;            // [KCB]
    float* vbuf = dyn + KCB;      // [NTOK]
    int d = blockIdx.x;
    int tid = threadIdx.x;
    const float* Wl = W + (size_t)l * KCB * DDIM + d;

    // ---- pre-dependency region: stage the W column (independent of g_pidx) ----
    scol[tid]       = Wl[(size_t)tid * DDIM];
    scol[tid + 256] = Wl[(size_t)(tid + 256) * DDIM];

    // ---- wait for reduce's g_pidx writes ----
    gdc_wait();
    __syncthreads();

    #pragma unroll
    for (int j = 0; j < NTOK / 256; j++) {
        int n = tid + j * 256;
        vbuf[n] = scol[g_pidx[n]];
    }
    __syncthreads();

    if (tid == 0) {
        float part = 0.f;
        const float4* b4 = (const float4*)vbuf;
        #pragma unroll 16
        for (int j = 0; j < NTOK / 4; j++) {
            float4 q = b4[j];
            part = __fadd_rn(part, q.x);
            part = __fadd_rn(part, q.y);
            part = __fadd_rn(part, q.z);
            part = __fadd_rn(part, q.w);
        }
        g_g[d] = __fadd_rn(g_g[d], part);
    }
}

// ---------------- q_out (transposed write) + per-token loss, 16 tokens/block ------
__global__ void k_final_q(const float* __restrict__ W, float* __restrict__ out,
                          long long o_q) {
    __shared__ int   sidx[16][8];
    __shared__ float sq[16][257];
    int tid = threadIdx.x;
    int tbase = blockIdx.x * 16;
    if (tid < 128) sidx[tid >> 3][tid & 7] = g_idx[(tbase + (tid >> 3)) * LLV + (tid & 7)];
    __syncthreads();

    int d = tid;
    for (int t = 0; t < 16; t++) {
        float acc = 0.f;
        #pragma unroll
        for (int l = 0; l < LLV; l++)
            acc = __fadd_rn(acc, W[(size_t)(l * KCB + sidx[t][l]) * DDIM + d]);
        sq[t][d] = acc;
    }
    if (tid < 16) {
        int n = tbase + tid;
        float nl = 0.f;
        float un = g_normW[sidx[tid][0]];
        #pragma unroll
        for (int l = 0; l < 7; l++) {
            float lo = g_normW[(l + 1) * KCB + sidx[tid][l + 1]];
            float r  = fmaxf(__fmul_rn(__fdiv_rn(lo, un), 4.0f), 1.0f) - 1.0f;
            nl = __fadd_rn(nl, __fmul_rn(r, r));
            un = lo;
        }
        float nlm = __fdiv_rn(nl, 7.0f);
        g_ltok[n] = __fadd_rn(g_kl[n], __fmul_rn(nlm, 0.1f));
    }
    __syncthreads();
    if (o_q >= 0) {
        int b   = tbase >> 10;
        int hw0 = tbase & 1023;
        float* dst = out + o_q + (size_t)b * (DDIM * 1024);
        for (int it = 0; it < 16; it++) {
            int e = it * 256 + tid;
            int t = e & 15;
            int dd = e >> 4;
            dst[(size_t)dd * 1024 + hw0 + t] = sq[t][dd];
        }
    }
}

// ---------------- per-batch loss mean (parallel tree; loss output is tolerant) -----
__global__ void k_final_loss(float* __restrict__ out, long long o_l) {
    __shared__ float sh[8];
    int b = blockIdx.x, tid = threadIdx.x;
    int warp = tid >> 5, lane = tid & 31;
    float s = 0.f;
    #pragma unroll
    for (int i = 0; i < 4; i++)
        s = __fadd_rn(s, g_ltok[b * 1024 + tid + i * 256]);
    #pragma unroll
    for (int o = 16; o; o >>= 1) s += __shfl_down_sync(0xffffffffu, s, o);
    if (lane == 0) sh[warp] = s;
    __syncthreads();
    if (tid == 0 && o_l >= 0) {
        float t = 0.f;
        #pragma unroll
        for (int wdx = 0; wdx < 8; wdx++) t = __fadd_rn(t, sh[wdx]);
        out[o_l + b] = t * (1.0f / 1024.0f);
    }
}

// ---------------- PDL launch helper ----------------
template <typename... Args>
static void launch_pdl(void (*kern)(Args...), dim3 grid, dim3 block, size_t smem,
                       Args... args) {
    cudaLaunchConfig_t cfg = {};
    cfg.gridDim  = grid;
    cfg.blockDim = block;
    cfg.dynamicSmemBytes = smem;
    cfg.stream   = 0;
    cudaLaunchAttribute attr[1];
    attr[0].id = cudaLaunchAttributeProgrammaticStreamSerialization;
    attr[0].val.programmaticStreamSerializationAllowed = 1;
    cfg.attrs = attr;
    cfg.numAttrs = 1;
    if (cudaLaunchKernelEx(&cfg, kern, args...) != cudaSuccess) {
        // fallback: plain launch (griddepcontrol.wait is a no-op without PDL)
        kern<<<grid, block, smem>>>(args...);
    }
}

// ---------------- launch (gemm/reduce/gchain all PDL-overlapped) ----------------
extern "C" void kernel_launch(void* const* d_in, const int* in_sizes, int n_in,
                              void* d_out, int out_size) {
    const float* z = nullptr;
    const float* w = nullptr;
    for (int i = 0; i < n_in; i++) {
        if (in_sizes[i] == NTOK * DDIM)            z = (const float*)d_in[i];
        else if (in_sizes[i] == LLV * KCB * DDIM)  w = (const float*)d_in[i];
    }
    float* out = (float*)d_out;

    const long long SZ_Q = (long long)BATCH * DDIM * 1024;   // 4194304
    const long long SZ_I = (long long)NTOK * LLV;            // 131072
    const long long SZ_L = BATCH;                            // 16
    const long long SZ_P = (long long)NTOK * LLV * KCB;      // 67108864
    long long o_q = 0, o_i = -1, o_l = -1, o_p = -1;
    long long total = SZ_Q + SZ_I + SZ_L + SZ_P;
    if ((long long)out_size >= total) { o_i = SZ_Q; o_l = o_i + SZ_I; o_p = o_l + SZ_L; }
    else cudaMemsetAsync(d_out, 0, (size_t)out_size * sizeof(float), 0);  // fallback only

    cudaFuncSetAttribute(k_gchain, cudaFuncAttributeMaxDynamicSharedMemorySize,
                         GCHAIN_SMEM);

    k_init<<<16, 256>>>(w);
    for (int l = 0; l < LLV; l++) {
        const float* wl = w + (size_t)l * KCB * DDIM;
        launch_pdl(k_gemm, dim3(4, 128), dim3(256), (size_t)0, z, wl);
        launch_pdl(k_reduce, dim3(2048), dim3(256), (size_t)0,
                   z, l, out, o_i, o_p);
        if (l < LLV - 1)
            launch_pdl(k_gchain, dim3(DDIM), dim3(256), (size_t)GCHAIN_SMEM, w, l);
    }
    k_final_q<<<1024, 256>>>(w, out, o_q);
    k_final_loss<<<BATCH, 256>>>(out, o_l);
}